// round 1
// baseline (speedup 1.0000x reference)
#include <cuda_runtime.h>
#include <math.h>

// Problem constants (fixed by the dataset)
#define S_LEN  8192
#define B_SZ   2
#define DM     1024
#define NH     16
#define DH     64
#define SEG    128
#define NSEG   (S_LEN / SEG)     // 64
#define GRID_G 91                // ceil(sqrt(8192))

// Scratch (allocation-free rule: __device__ globals)
__device__ float g_qkv[2 * 8192 * 3 * 1024];   // [B,S,3,H,Dh] = [16384, 3072]
__device__ float g_attn[2 * 8192 * 1024];      // [B,S,H*Dh]   = [16384, 1024]
__device__ int   g_map[S_LEN];

// ---------------------------------------------------------------------------
// Boustrophedon ("Hilbert") permutation map, closed form.
// All rows strictly before the S boundary are fully valid, so:
//   even row: fm[lp] = r*g + c
//   odd  row: fm[lp] = r*g + (vr - 1 - c),  vr = min(g, S - r*g)
// ---------------------------------------------------------------------------
__global__ void map_kernel() {
    int lp = blockIdx.x * 256 + threadIdx.x;
    if (lp >= S_LEN) return;
    int r = lp / GRID_G;
    int c = lp % GRID_G;
    int vr = min(GRID_G, S_LEN - r * GRID_G);
    g_map[lp] = ((r & 1) == 0) ? (r * GRID_G + c) : (r * GRID_G + vr - 1 - c);
}

// ---------------------------------------------------------------------------
// Tiled fp32 GEMM: C[M,N] = A[M,K] @ B[K,N], all row-major.
// BM=BN=128, BK=16, TM=TN=8, 256 threads. Dims are multiples of tile sizes.
// ---------------------------------------------------------------------------
#define BM 128
#define BN 128
#define BK 16
#define TM 8
#define TN 8

__global__ __launch_bounds__(256) void sgemm_tiled(
    int M, int N, int K,
    const float* __restrict__ A,
    const float* __restrict__ B,
    float* __restrict__ C)
{
    __shared__ float As[BK][BM];   // transposed store: As[k][m]
    __shared__ float Bs[BK][BN];

    const int bx = blockIdx.x;     // N tile
    const int by = blockIdx.y;     // M tile
    const int tid = threadIdx.x;

    A += (size_t)by * BM * K;
    B += (size_t)bx * BN;
    C += (size_t)by * BM * N + (size_t)bx * BN;

    const int threadCol = tid % (BN / TN);   // 0..15
    const int threadRow = tid / (BN / TN);   // 0..15

    // A tile loads: 128x16 floats -> float4: row = tid/4 (0..63, +64), col = (tid%4)*4
    const int aRow = tid / (BK / 4);
    const int aCol = (tid % (BK / 4)) * 4;
    // B tile loads: 16x128 floats -> float4: row = tid/32 (0..7, +8), col = (tid%32)*4
    const int bRow = tid / (BN / 4);
    const int bCol = (tid % (BN / 4)) * 4;

    float acc[TM][TN] = {};
    float regM[TM], regN[TN];

    for (int k0 = 0; k0 < K; k0 += BK) {
        // Load A tile (transposed into As)
        #pragma unroll
        for (int r = 0; r < BM; r += 64) {
            float4 t = *(const float4*)(A + (size_t)(aRow + r) * K + aCol);
            As[aCol + 0][aRow + r] = t.x;
            As[aCol + 1][aRow + r] = t.y;
            As[aCol + 2][aRow + r] = t.z;
            As[aCol + 3][aRow + r] = t.w;
        }
        // Load B tile
        #pragma unroll
        for (int r = 0; r < BK; r += 8) {
            *(float4*)(&Bs[bRow + r][bCol]) =
                *(const float4*)(B + (size_t)(bRow + r) * N + bCol);
        }
        __syncthreads();

        A += BK;
        B += (size_t)BK * N;

        #pragma unroll
        for (int kk = 0; kk < BK; kk++) {
            #pragma unroll
            for (int i = 0; i < TM; i += 4) {
                float4 t = *(const float4*)(&As[kk][threadRow * TM + i]);
                regM[i] = t.x; regM[i+1] = t.y; regM[i+2] = t.z; regM[i+3] = t.w;
            }
            #pragma unroll
            for (int j = 0; j < TN; j += 4) {
                float4 t = *(const float4*)(&Bs[kk][threadCol * TN + j]);
                regN[j] = t.x; regN[j+1] = t.y; regN[j+2] = t.z; regN[j+3] = t.w;
            }
            #pragma unroll
            for (int i = 0; i < TM; i++)
                #pragma unroll
                for (int j = 0; j < TN; j++)
                    acc[i][j] += regM[i] * regN[j];
        }
        __syncthreads();
    }

    #pragma unroll
    for (int i = 0; i < TM; i++) {
        #pragma unroll
        for (int j = 0; j < TN; j += 4) {
            float4 t = make_float4(acc[i][j], acc[i][j+1], acc[i][j+2], acc[i][j+3]);
            *(float4*)(C + (size_t)(threadRow * TM + i) * N + threadCol * TN + j) = t;
        }
    }
}

// ---------------------------------------------------------------------------
// Fused segment attention over the permuted sequence.
// One block per (b, h, segment). 128 threads, one query row each.
// K/V rows are the even permuted positions (dilation=2) -> 64 keys of Dh=64.
// Shared: KV[64][64] (K in phase 1, reloaded with V for phase 2) +
//         Pt[64][128] (scores then probabilities, column-per-thread).
// Output scattered back to seq row m[p] in [B,S,H*Dh] layout.
// ---------------------------------------------------------------------------
__global__ __launch_bounds__(128) void attn_kernel() {
    __shared__ float KV[64][64];     // 16 KB
    __shared__ float Pt[64][128];    // 32 KB  (total 48 KB static)

    const int bid = blockIdx.x;
    const int n = bid % NSEG;
    const int h = (bid / NSEG) % NH;
    const int b = bid / (NSEG * NH);
    const int tid = threadIdx.x;

    const int j0   = tid >> 1;         // key row this thread helps load
    const int half = (tid & 1) * 32;   // which 32-float half
    const int skv  = g_map[n * SEG + 2 * j0];

    // Load K tile
    {
        const float4* src = (const float4*)(g_qkv +
            ((size_t)(b * S_LEN + skv)) * 3 * DM + DM + h * DH + half);
        float4* dst = (float4*)&KV[j0][half];
        #pragma unroll
        for (int i = 0; i < 8; i++) dst[i] = src[i];
    }

    // Load this thread's query row into registers
    float q[DH];
    const int sq = g_map[n * SEG + tid];
    {
        const float4* qp = (const float4*)(g_qkv +
            ((size_t)(b * S_LEN + sq)) * 3 * DM + h * DH);
        #pragma unroll
        for (int i = 0; i < 16; i++) {
            float4 t = qp[i];
            q[4*i] = t.x; q[4*i+1] = t.y; q[4*i+2] = t.z; q[4*i+3] = t.w;
        }
    }
    __syncthreads();

    // Phase 1: scores = (q . k_j) * scale, track row max
    float mx = -1e30f;
    for (int j = 0; j < 64; j++) {
        const float4* kr = (const float4*)KV[j];   // broadcast across warp
        float s = 0.0f;
        #pragma unroll
        for (int d = 0; d < 16; d++) {
            float4 kk = kr[d];
            s += q[4*d]   * kk.x + q[4*d+1] * kk.y
               + q[4*d+2] * kk.z + q[4*d+3] * kk.w;
        }
        s *= 0.125f;   // Dh^-0.5
        mx = fmaxf(mx, s);
        Pt[j][tid] = s;
    }

    // Softmax numerator + denominator (each thread owns its row entirely)
    float sum = 0.0f;
    for (int j = 0; j < 64; j++) {
        float p = expf(Pt[j][tid] - mx);
        sum += p;
        Pt[j][tid] = p;
    }
    __syncthreads();   // everyone done with K

    // Load V tile into the same buffer
    {
        const float4* src = (const float4*)(g_qkv +
            ((size_t)(b * S_LEN + skv)) * 3 * DM + 2 * DM + h * DH + half);
        float4* dst = (float4*)&KV[j0][half];
        #pragma unroll
        for (int i = 0; i < 8; i++) dst[i] = src[i];
    }
    __syncthreads();

    // Phase 2: out = P @ V
    float4 out[16];
    #pragma unroll
    for (int i = 0; i < 16; i++) out[i] = make_float4(0.f, 0.f, 0.f, 0.f);

    for (int j = 0; j < 64; j++) {
        float p = Pt[j][tid];
        const float4* vr = (const float4*)KV[j];   // broadcast
        #pragma unroll
        for (int d = 0; d < 16; d++) {
            float4 vv = vr[d];
            out[d].x += p * vv.x; out[d].y += p * vv.y;
            out[d].z += p * vv.z; out[d].w += p * vv.w;
        }
    }

    const float inv = 1.0f / sum;
    float4* op = (float4*)(g_attn + ((size_t)(b * S_LEN + sq)) * DM + h * DH);
    #pragma unroll
    for (int i = 0; i < 16; i++) {
        out[i].x *= inv; out[i].y *= inv; out[i].z *= inv; out[i].w *= inv;
        op[i] = out[i];
    }
}

// ---------------------------------------------------------------------------
// Launch
// ---------------------------------------------------------------------------
extern "C" void kernel_launch(void* const* d_in, const int* in_sizes, int n_in,
                              void* d_out, int out_size)
{
    const float* x     = (const float*)d_in[0];   // [2,8192,1024]
    const float* wqkv  = (const float*)d_in[1];   // [1024,3072]
    const float* wout  = (const float*)d_in[2];   // [1024,1024]
    float*       out   = (float*)d_out;           // [2,8192,1024]

    float *qkv_ptr = nullptr, *attn_ptr = nullptr;
    cudaGetSymbolAddress((void**)&qkv_ptr, g_qkv);
    cudaGetSymbolAddress((void**)&attn_ptr, g_attn);

    // 1. permutation map
    map_kernel<<<(S_LEN + 255) / 256, 256>>>();

    // 2. QKV projection: [16384,1024] @ [1024,3072]
    {
        dim3 grid((3 * DM) / BN, (B_SZ * S_LEN) / BM);
        sgemm_tiled<<<grid, 256>>>(B_SZ * S_LEN, 3 * DM, DM, x, wqkv, qkv_ptr);
    }

    // 3. segment attention (gather by map, scatter by map)
    attn_kernel<<<B_SZ * NH * NSEG, 128>>>();

    // 4. output projection: [16384,1024] @ [1024,1024]
    {
        dim3 grid(DM / BN, (B_SZ * S_LEN) / BM);
        sgemm_tiled<<<grid, 256>>>(B_SZ * S_LEN, DM, DM, attn_ptr, wout, out);
    }
}

// round 3
// speedup vs baseline: 2.0432x; 2.0432x over previous
#include <cuda_runtime.h>
#include <cuda_bf16.h>
#include <cstdint>
#include <math.h>

// Problem constants (fixed by the dataset)
#define S_LEN  8192
#define B_SZ   2
#define DM     1024
#define NH     16
#define DH     64
#define SEG    128
#define NSEG   (S_LEN / SEG)     // 64
#define GRID_G 91                // ceil(sqrt(8192))

#define MROWS  (B_SZ * S_LEN)    // 16384

// ---------------------------------------------------------------------------
// Scratch (allocation-free rule: __device__ globals)
// ---------------------------------------------------------------------------
__device__ float          g_qkv [MROWS * 3 * DM];      // fp32 [B,S,3,H,Dh]
__device__ float          g_attn[MROWS * DM];          // fp32
__device__ __nv_bfloat16  g_xhi [MROWS * DM];          // x split hi
__device__ __nv_bfloat16  g_xlo [MROWS * DM];
__device__ __nv_bfloat16  g_ahi [MROWS * DM];          // attn split hi
__device__ __nv_bfloat16  g_alo [MROWS * DM];
__device__ __nv_bfloat16  g_wqh [3 * DM * DM];         // W_qkv^T split [3072,1024]
__device__ __nv_bfloat16  g_wql [3 * DM * DM];
__device__ __nv_bfloat16  g_woh [DM * DM];             // W_out^T split [1024,1024]
__device__ __nv_bfloat16  g_wol [DM * DM];
__device__ int            g_map [S_LEN];

// ---------------------------------------------------------------------------
// PTX helpers (compute_103-safe subset: ldmatrix / mma.sync / cp.async)
// ---------------------------------------------------------------------------
__device__ __forceinline__ uint32_t smem_to_u32(const void* p) {
    uint32_t a;
    asm("{ .reg .u64 t; cvta.to.shared.u64 t, %1; cvt.u32.u64 %0, t; }"
        : "=r"(a) : "l"(p));
    return a;
}
__device__ __forceinline__ void cp_async16(uint32_t saddr, const void* gptr) {
    asm volatile("cp.async.cg.shared.global [%0], [%1], 16;"
                 :: "r"(saddr), "l"(gptr));
}
#define CP_COMMIT() asm volatile("cp.async.commit_group;")
#define CP_WAIT(n)  asm volatile("cp.async.wait_group %0;" :: "n"(n))

__device__ __forceinline__ void ldsm_x4(uint32_t& r0, uint32_t& r1,
                                        uint32_t& r2, uint32_t& r3,
                                        uint32_t addr) {
    asm volatile("ldmatrix.sync.aligned.m8n8.x4.shared.b16 {%0,%1,%2,%3}, [%4];"
                 : "=r"(r0), "=r"(r1), "=r"(r2), "=r"(r3) : "r"(addr));
}
__device__ __forceinline__ void mma16816(float* c,
                                         uint32_t a0, uint32_t a1,
                                         uint32_t a2, uint32_t a3,
                                         uint32_t b0, uint32_t b1) {
    asm volatile(
        "mma.sync.aligned.m16n8k16.row.col.f32.bf16.bf16.f32 "
        "{%0,%1,%2,%3}, {%4,%5,%6,%7}, {%8,%9}, {%0,%1,%2,%3};"
        : "+f"(c[0]), "+f"(c[1]), "+f"(c[2]), "+f"(c[3])
        : "r"(a0), "r"(a1), "r"(a2), "r"(a3), "r"(b0), "r"(b1));
}

// ---------------------------------------------------------------------------
// Boustrophedon ("Hilbert") permutation map, closed form
// ---------------------------------------------------------------------------
__global__ void map_kernel() {
    int lp = blockIdx.x * 256 + threadIdx.x;
    if (lp >= S_LEN) return;
    int r = lp / GRID_G;
    int c = lp % GRID_G;
    int vr = min(GRID_G, S_LEN - r * GRID_G);
    g_map[lp] = ((r & 1) == 0) ? (r * GRID_G + c) : (r * GRID_G + vr - 1 - c);
}

// ---------------------------------------------------------------------------
// fp32 -> (bf16 hi, bf16 lo) elementwise split
// ---------------------------------------------------------------------------
__global__ __launch_bounds__(256) void split_kernel(
    const float* __restrict__ src, __nv_bfloat16* __restrict__ hi,
    __nv_bfloat16* __restrict__ lo, int n4)
{
    int i = blockIdx.x * 256 + threadIdx.x;
    if (i >= n4) return;
    float4 v = ((const float4*)src)[i];
    __nv_bfloat16 hx = __float2bfloat16_rn(v.x);
    __nv_bfloat16 hy = __float2bfloat16_rn(v.y);
    __nv_bfloat16 hz = __float2bfloat16_rn(v.z);
    __nv_bfloat16 hw = __float2bfloat16_rn(v.w);
    __nv_bfloat162* hp = (__nv_bfloat162*)hi;
    __nv_bfloat162* lp = (__nv_bfloat162*)lo;
    hp[2 * i]     = __nv_bfloat162(hx, hy);
    hp[2 * i + 1] = __nv_bfloat162(hz, hw);
    lp[2 * i]     = __nv_bfloat162(__float2bfloat16_rn(v.x - __bfloat162float(hx)),
                                   __float2bfloat16_rn(v.y - __bfloat162float(hy)));
    lp[2 * i + 1] = __nv_bfloat162(__float2bfloat16_rn(v.z - __bfloat162float(hz)),
                                   __float2bfloat16_rn(v.w - __bfloat162float(hw)));
}

// ---------------------------------------------------------------------------
// W [K,N] fp32 -> W^T [N,K] bf16 hi/lo (tiled transpose + split)
// ---------------------------------------------------------------------------
__global__ __launch_bounds__(256) void transpose_split_kernel(
    const float* __restrict__ W, __nv_bfloat16* __restrict__ Thi,
    __nv_bfloat16* __restrict__ Tlo, int K, int N)
{
    __shared__ float t[32][33];
    int n0 = blockIdx.x * 32, k0 = blockIdx.y * 32;
    int tx = threadIdx.x, ty = threadIdx.y;    // block (32, 8)
    #pragma unroll
    for (int i = 0; i < 4; i++)
        t[ty + 8 * i][tx] = W[(size_t)(k0 + ty + 8 * i) * N + n0 + tx];
    __syncthreads();
    #pragma unroll
    for (int i = 0; i < 4; i++) {
        float v = t[tx][ty + 8 * i];
        __nv_bfloat16 h = __float2bfloat16_rn(v);
        size_t o = (size_t)(n0 + ty + 8 * i) * K + k0 + tx;
        Thi[o] = h;
        Tlo[o] = __float2bfloat16_rn(v - __bfloat162float(h));
    }
}

// ---------------------------------------------------------------------------
// HMMA bf16x3-split GEMM: C[M,N] = (Ah+Al)[M,K] @ (Bh+Bl)[N,K]^T  (fp32 out)
// BM=128, BN=256, BK=32, 256 threads (8 warps, warptile 64x64), cp.async
// double buffer. Smem rows padded to 40 bf16 (80B) -> conflict-free ldmatrix.
// ---------------------------------------------------------------------------
#define GBM 128
#define GBN 256
#define GBK 32
#define RSTRIDE 40                     // bf16 elems per smem row (32 + 8 pad)
#define RSB     (RSTRIDE * 2)          // 80 bytes
#define OFF_AH  0
#define OFF_AL  (GBM * RSB)            // 10240
#define OFF_BH  (2 * GBM * RSB)        // 20480
#define OFF_BL  (2 * GBM * RSB + GBN * RSB)   // 40960
#define STAGE_BYTES (2 * GBM * RSB + 2 * GBN * RSB)  // 61440
#define GEMM_SMEM (2 * STAGE_BYTES)    // 122880

__global__ __launch_bounds__(256, 1) void gemm_bf16x3(
    int M, int N, int K,
    const __nv_bfloat16* __restrict__ Ah, const __nv_bfloat16* __restrict__ Al,
    const __nv_bfloat16* __restrict__ Bh, const __nv_bfloat16* __restrict__ Bl,
    float* __restrict__ C)
{
    extern __shared__ char smem[];
    const uint32_t sb = smem_to_u32(smem);
    const int tid  = threadIdx.x;
    const int wid  = tid >> 5;
    const int lane = tid & 31;

    const int m0 = blockIdx.y * GBM;
    const int n0 = blockIdx.x * GBN;
    const int iters = K >> 5;          // K / 32

    const int warp_m = (wid & 1) * 64;       // 0 or 64
    const int warp_n = (wid >> 1) * 64;      // 0,64,128,192

    float acc[4][8][4];
    #pragma unroll
    for (int i = 0; i < 4; i++)
        #pragma unroll
        for (int j = 0; j < 8; j++)
            #pragma unroll
            for (int q = 0; q < 4; q++) acc[i][j][q] = 0.0f;

    // ---- tile loader: 3072 16B chunks per stage, 12 per thread ----
    auto load_stage = [&](int it, int stage) {
        const uint32_t stg = sb + stage * STAGE_BYTES;
        const int k0 = it * GBK;
        #pragma unroll
        for (int i = 0; i < 12; i++) {
            int c = i * 256 + tid;
            const __nv_bfloat16* g;
            uint32_t soff;
            if (c < 1024) {            // A hi/lo: 2 mats x 128 rows x 4 chunks
                int mat = c >> 9;      // 0=Ah 1=Al
                int rk  = c & 511;
                int row = rk >> 2, kc = rk & 3;
                g = (mat ? Al : Ah) + (size_t)(m0 + row) * K + k0 + kc * 8;
                soff = (mat ? OFF_AL : OFF_AH) + row * RSB + kc * 16;
            } else {                   // B hi/lo: 2 mats x 256 rows x 4 chunks
                int c2 = c - 1024;
                int mat = c2 >> 10;
                int rk  = c2 & 1023;
                int row = rk >> 2, kc = rk & 3;
                g = (mat ? Bl : Bh) + (size_t)(n0 + row) * K + k0 + kc * 8;
                soff = (mat ? OFF_BL : OFF_BH) + row * RSB + kc * 16;
            }
            cp_async16(stg + soff, g);
        }
    };

    load_stage(0, 0);
    CP_COMMIT();

    // lane-dependent ldmatrix address components
    const int a_row  = lane & 15;            // row within 16-row A tile
    const int a_byte = (lane >> 4) << 4;     // 0 or 16 (k half)
    const int b_row  = ((lane >> 4) << 3) + (lane & 7);   // row within 16-n pair
    const int b_byte = ((lane >> 3) & 1) << 4;            // 0 or 16

    #pragma unroll 1
    for (int it = 0; it < iters; ++it) {
        if (it + 1 < iters) {
            load_stage(it + 1, (it + 1) & 1);
            CP_COMMIT();
            CP_WAIT(1);
        } else {
            CP_WAIT(0);
        }
        __syncthreads();

        const uint32_t stg = sb + (it & 1) * STAGE_BYTES;
        const uint32_t aARow = stg + (warp_m + a_row) * RSB + a_byte;
        const uint32_t aBRow = stg + (warp_n + b_row) * RSB + b_byte;

        #pragma unroll
        for (int kc = 0; kc < 2; kc++) {
            const uint32_t kb = kc * 32;
            uint32_t ah[4][4], al[4][4], bh[8][2], bl[8][2];
            #pragma unroll
            for (int i = 0; i < 4; i++) {
                ldsm_x4(ah[i][0], ah[i][1], ah[i][2], ah[i][3],
                        aARow + OFF_AH + i * 16 * RSB + kb);
                ldsm_x4(al[i][0], al[i][1], al[i][2], al[i][3],
                        aARow + OFF_AL + i * 16 * RSB + kb);
            }
            #pragma unroll
            for (int jj = 0; jj < 4; jj++) {
                ldsm_x4(bh[2*jj][0], bh[2*jj][1], bh[2*jj+1][0], bh[2*jj+1][1],
                        aBRow + OFF_BH + jj * 16 * RSB + kb);
                ldsm_x4(bl[2*jj][0], bl[2*jj][1], bl[2*jj+1][0], bl[2*jj+1][1],
                        aBRow + OFF_BL + jj * 16 * RSB + kb);
            }
            #pragma unroll
            for (int i = 0; i < 4; i++)
                #pragma unroll
                for (int j = 0; j < 8; j++) {
                    mma16816(acc[i][j], ah[i][0], ah[i][1], ah[i][2], ah[i][3],
                             bh[j][0], bh[j][1]);
                    mma16816(acc[i][j], ah[i][0], ah[i][1], ah[i][2], ah[i][3],
                             bl[j][0], bl[j][1]);
                    mma16816(acc[i][j], al[i][0], al[i][1], al[i][2], al[i][3],
                             bh[j][0], bh[j][1]);
                }
        }
        __syncthreads();
    }

    // ---- epilogue: fragment -> global fp32 ----
    const int er = lane >> 2;          // 0..7
    const int ec = (lane & 3) * 2;     // 0,2,4,6
    #pragma unroll
    for (int i = 0; i < 4; i++) {
        #pragma unroll
        for (int j = 0; j < 8; j++) {
            int row = m0 + warp_m + i * 16 + er;
            int col = n0 + warp_n + j * 8 + ec;
            float* p0 = C + (size_t)row * N + col;
            float* p1 = C + (size_t)(row + 8) * N + col;
            p0[0] = acc[i][j][0]; p0[1] = acc[i][j][1];
            p1[0] = acc[i][j][2]; p1[1] = acc[i][j][3];
        }
    }
}

// ---------------------------------------------------------------------------
// Fused segment attention over the permuted sequence (fp32)
// ---------------------------------------------------------------------------
__global__ __launch_bounds__(128) void attn_kernel() {
    __shared__ float KV[64][64];     // 16 KB
    __shared__ float Pt[64][128];    // 32 KB

    const int bid = blockIdx.x;
    const int n = bid % NSEG;
    const int h = (bid / NSEG) % NH;
    const int b = bid / (NSEG * NH);
    const int tid = threadIdx.x;

    const int j0   = tid >> 1;
    const int half = (tid & 1) * 32;
    const int skv  = g_map[n * SEG + 2 * j0];

    {
        const float4* src = (const float4*)(g_qkv +
            ((size_t)(b * S_LEN + skv)) * 3 * DM + DM + h * DH + half);
        float4* dst = (float4*)&KV[j0][half];
        #pragma unroll
        for (int i = 0; i < 8; i++) dst[i] = src[i];
    }

    float q[DH];
    const int sq = g_map[n * SEG + tid];
    {
        const float4* qp = (const float4*)(g_qkv +
            ((size_t)(b * S_LEN + sq)) * 3 * DM + h * DH);
        #pragma unroll
        for (int i = 0; i < 16; i++) {
            float4 t = qp[i];
            q[4*i] = t.x; q[4*i+1] = t.y; q[4*i+2] = t.z; q[4*i+3] = t.w;
        }
    }
    __syncthreads();

    float mx = -1e30f;
    for (int j = 0; j < 64; j++) {
        const float4* kr = (const float4*)KV[j];
        float s = 0.0f;
        #pragma unroll
        for (int d = 0; d < 16; d++) {
            float4 kk = kr[d];
            s += q[4*d]   * kk.x + q[4*d+1] * kk.y
               + q[4*d+2] * kk.z + q[4*d+3] * kk.w;
        }
        s *= 0.125f;
        mx = fmaxf(mx, s);
        Pt[j][tid] = s;
    }

    float sum = 0.0f;
    for (int j = 0; j < 64; j++) {
        float p = expf(Pt[j][tid] - mx);
        sum += p;
        Pt[j][tid] = p;
    }
    __syncthreads();

    {
        const float4* src = (const float4*)(g_qkv +
            ((size_t)(b * S_LEN + skv)) * 3 * DM + 2 * DM + h * DH + half);
        float4* dst = (float4*)&KV[j0][half];
        #pragma unroll
        for (int i = 0; i < 8; i++) dst[i] = src[i];
    }
    __syncthreads();

    float4 out[16];
    #pragma unroll
    for (int i = 0; i < 16; i++) out[i] = make_float4(0.f, 0.f, 0.f, 0.f);

    for (int j = 0; j < 64; j++) {
        float p = Pt[j][tid];
        const float4* vr = (const float4*)KV[j];
        #pragma unroll
        for (int d = 0; d < 16; d++) {
            float4 vv = vr[d];
            out[d].x += p * vv.x; out[d].y += p * vv.y;
            out[d].z += p * vv.z; out[d].w += p * vv.w;
        }
    }

    const float inv = 1.0f / sum;
    float4* op = (float4*)(g_attn + ((size_t)(b * S_LEN + sq)) * DM + h * DH);
    #pragma unroll
    for (int i = 0; i < 16; i++) {
        out[i].x *= inv; out[i].y *= inv; out[i].z *= inv; out[i].w *= inv;
        op[i] = out[i];
    }
}

// ---------------------------------------------------------------------------
// Launch
// ---------------------------------------------------------------------------
extern "C" void kernel_launch(void* const* d_in, const int* in_sizes, int n_in,
                              void* d_out, int out_size)
{
    const float* x    = (const float*)d_in[0];   // [2,8192,1024]
    const float* wqkv = (const float*)d_in[1];   // [1024,3072]
    const float* wout = (const float*)d_in[2];   // [1024,1024]
    float*       out  = (float*)d_out;           // [2,8192,1024]

    float *qkv_p = nullptr, *attn_p = nullptr;
    __nv_bfloat16 *xhi, *xlo, *ahi, *alo, *wqh, *wql, *woh, *wol;
    cudaGetSymbolAddress((void**)&qkv_p,  g_qkv);
    cudaGetSymbolAddress((void**)&attn_p, g_attn);
    cudaGetSymbolAddress((void**)&xhi, g_xhi);
    cudaGetSymbolAddress((void**)&xlo, g_xlo);
    cudaGetSymbolAddress((void**)&ahi, g_ahi);
    cudaGetSymbolAddress((void**)&alo, g_alo);
    cudaGetSymbolAddress((void**)&wqh, g_wqh);
    cudaGetSymbolAddress((void**)&wql, g_wql);
    cudaGetSymbolAddress((void**)&woh, g_woh);
    cudaGetSymbolAddress((void**)&wol, g_wol);

    static bool attr_set = false;
    if (!attr_set) {
        cudaFuncSetAttribute(gemm_bf16x3,
            cudaFuncAttributeMaxDynamicSharedMemorySize, GEMM_SMEM);
        attr_set = true;
    }

    // 1. permutation map + operand preparation
    map_kernel<<<(S_LEN + 255) / 256, 256>>>();
    split_kernel<<<(MROWS * DM / 4 + 255) / 256, 256>>>(x, xhi, xlo, MROWS * DM / 4);
    {
        dim3 blk(32, 8);
        transpose_split_kernel<<<dim3(3 * DM / 32, DM / 32), blk>>>(wqkv, wqh, wql, DM, 3 * DM);
        transpose_split_kernel<<<dim3(DM / 32, DM / 32), blk>>>(wout, woh, wol, DM, DM);
    }

    // 2. QKV projection: [16384,1024] @ [1024,3072] (HMMA bf16 x3 split)
    gemm_bf16x3<<<dim3(3 * DM / GBN, MROWS / GBM), 256, GEMM_SMEM>>>(
        MROWS, 3 * DM, DM, xhi, xlo, wqh, wql, qkv_p);

    // 3. segment attention (gather by map, scatter by map)
    attn_kernel<<<B_SZ * NH * NSEG, 128>>>();

    // 4. output projection: [16384,1024] @ [1024,1024]
    split_kernel<<<(MROWS * DM / 4 + 255) / 256, 256>>>(attn_p, ahi, alo, MROWS * DM / 4);
    gemm_bf16x3<<<dim3(DM / GBN, MROWS / GBM), 256, GEMM_SMEM>>>(
        MROWS, DM, DM, ahi, alo, woh, wol, out);
}

// round 4
// speedup vs baseline: 2.4204x; 1.1846x over previous
#include <cuda_runtime.h>
#include <cuda_bf16.h>
#include <cstdint>
#include <math.h>

// Problem constants (fixed by the dataset)
#define S_LEN  8192
#define B_SZ   2
#define DM     1024
#define NH     16
#define DH     64
#define SEG    128
#define NSEG   (S_LEN / SEG)     // 64
#define GRID_G 91                // ceil(sqrt(8192))

#define MROWS  (B_SZ * S_LEN)    // 16384
#define KVROWS (B_SZ * S_LEN / 2)  // 8192 compacted K/V rows

// ---------------------------------------------------------------------------
// Scratch (allocation-free rule: __device__ globals)
// ---------------------------------------------------------------------------
__device__ float          g_q  [MROWS * DM];           // Q fp32 [B*S, H*Dh]
__device__ float          g_kv [KVROWS * 2 * DM];      // compact [B*4096, K|V]
__device__ __nv_bfloat16  g_xhi[MROWS * DM];           // x split hi
__device__ __nv_bfloat16  g_xlo[MROWS * DM];
__device__ __nv_bfloat16  g_ahi[MROWS * DM];           // attn-out split hi
__device__ __nv_bfloat16  g_alo[MROWS * DM];
__device__ __nv_bfloat16  g_wqh[3 * DM * DM];          // W_qkv^T split [3072,1024]
__device__ __nv_bfloat16  g_wql[3 * DM * DM];
__device__ __nv_bfloat16  g_woh[DM * DM];              // W_out^T split [1024,1024]
__device__ __nv_bfloat16  g_wol[DM * DM];
__device__ int            g_map  [S_LEN];
__device__ int            g_rowkv[KVROWS];             // gathered A rows for K/V GEMM

// ---------------------------------------------------------------------------
// PTX helpers (compute_103-safe subset: ldmatrix / mma.sync / cp.async)
// ---------------------------------------------------------------------------
__device__ __forceinline__ uint32_t smem_to_u32(const void* p) {
    uint32_t a;
    asm("{ .reg .u64 t; cvta.to.shared.u64 t, %1; cvt.u32.u64 %0, t; }"
        : "=r"(a) : "l"(p));
    return a;
}
__device__ __forceinline__ void cp_async16(uint32_t saddr, const void* gptr) {
    asm volatile("cp.async.cg.shared.global [%0], [%1], 16;"
                 :: "r"(saddr), "l"(gptr));
}
#define CP_COMMIT() asm volatile("cp.async.commit_group;")
#define CP_WAIT(n)  asm volatile("cp.async.wait_group %0;" :: "n"(n))

__device__ __forceinline__ void ldsm_x4(uint32_t& r0, uint32_t& r1,
                                        uint32_t& r2, uint32_t& r3,
                                        uint32_t addr) {
    asm volatile("ldmatrix.sync.aligned.m8n8.x4.shared.b16 {%0,%1,%2,%3}, [%4];"
                 : "=r"(r0), "=r"(r1), "=r"(r2), "=r"(r3) : "r"(addr));
}
__device__ __forceinline__ void mma16816(float* c,
                                         uint32_t a0, uint32_t a1,
                                         uint32_t a2, uint32_t a3,
                                         uint32_t b0, uint32_t b1) {
    asm volatile(
        "mma.sync.aligned.m16n8k16.row.col.f32.bf16.bf16.f32 "
        "{%0,%1,%2,%3}, {%4,%5,%6,%7}, {%8,%9}, {%0,%1,%2,%3};"
        : "+f"(c[0]), "+f"(c[1]), "+f"(c[2]), "+f"(c[3])
        : "r"(a0), "r"(a1), "r"(a2), "r"(a3), "r"(b0), "r"(b1));
}

// ---------------------------------------------------------------------------
// Closed-form boustrophedon map
// ---------------------------------------------------------------------------
__device__ __forceinline__ int hmap(int lp) {
    int r = lp / GRID_G;
    int c = lp % GRID_G;
    int vr = min(GRID_G, S_LEN - r * GRID_G);
    return ((r & 1) == 0) ? (r * GRID_G + c) : (r * GRID_G + vr - 1 - c);
}

__global__ void map_kernel() {
    int lp = blockIdx.x * 256 + threadIdx.x;
    if (lp < S_LEN) g_map[lp] = hmap(lp);
}

// Row list for the gathered K/V GEMM: compact row (b, n, j) <- x row b*S + m[n*128+2j]
__global__ void rowkv_kernel() {
    int i = blockIdx.x * 256 + threadIdx.x;
    if (i >= KVROWS) return;
    int b = i >> 12;           // /4096
    int r = i & 4095;
    int n = r >> 6, j = r & 63;
    g_rowkv[i] = b * S_LEN + hmap(n * SEG + 2 * j);
}

// ---------------------------------------------------------------------------
// fp32 -> (bf16 hi, bf16 lo) elementwise split
// ---------------------------------------------------------------------------
__global__ __launch_bounds__(256) void split_kernel(
    const float* __restrict__ src, __nv_bfloat16* __restrict__ hi,
    __nv_bfloat16* __restrict__ lo, int n4)
{
    int i = blockIdx.x * 256 + threadIdx.x;
    if (i >= n4) return;
    float4 v = ((const float4*)src)[i];
    __nv_bfloat16 hx = __float2bfloat16_rn(v.x);
    __nv_bfloat16 hy = __float2bfloat16_rn(v.y);
    __nv_bfloat16 hz = __float2bfloat16_rn(v.z);
    __nv_bfloat16 hw = __float2bfloat16_rn(v.w);
    __nv_bfloat162* hp = (__nv_bfloat162*)hi;
    __nv_bfloat162* lp = (__nv_bfloat162*)lo;
    hp[2 * i]     = __nv_bfloat162(hx, hy);
    hp[2 * i + 1] = __nv_bfloat162(hz, hw);
    lp[2 * i]     = __nv_bfloat162(__float2bfloat16_rn(v.x - __bfloat162float(hx)),
                                   __float2bfloat16_rn(v.y - __bfloat162float(hy)));
    lp[2 * i + 1] = __nv_bfloat162(__float2bfloat16_rn(v.z - __bfloat162float(hz)),
                                   __float2bfloat16_rn(v.w - __bfloat162float(hw)));
}

// ---------------------------------------------------------------------------
// W [K,N] fp32 -> W^T [N,K] bf16 hi/lo (tiled transpose + split)
// ---------------------------------------------------------------------------
__global__ __launch_bounds__(256) void transpose_split_kernel(
    const float* __restrict__ W, __nv_bfloat16* __restrict__ Thi,
    __nv_bfloat16* __restrict__ Tlo, int K, int N)
{
    __shared__ float t[32][33];
    int n0 = blockIdx.x * 32, k0 = blockIdx.y * 32;
    int tx = threadIdx.x, ty = threadIdx.y;    // block (32, 8)
    #pragma unroll
    for (int i = 0; i < 4; i++)
        t[ty + 8 * i][tx] = W[(size_t)(k0 + ty + 8 * i) * N + n0 + tx];
    __syncthreads();
    #pragma unroll
    for (int i = 0; i < 4; i++) {
        float v = t[tx][ty + 8 * i];
        __nv_bfloat16 h = __float2bfloat16_rn(v);
        size_t o = (size_t)(n0 + ty + 8 * i) * K + k0 + tx;
        Thi[o] = h;
        Tlo[o] = __float2bfloat16_rn(v - __bfloat162float(h));
    }
}

// ---------------------------------------------------------------------------
// HMMA bf16x3-split GEMM with optional gathered A rows.
// C[M,N] = (Ah+Al)[rows][K] @ (Bh+Bl)[N,K]^T, fp32 out.
// BM=128, BN=256, BK=32, 256 threads, 3-stage cp.async pipeline.
// ---------------------------------------------------------------------------
#define GBM 128
#define GBN 256
#define GBK 32
#define RSTRIDE 40                     // bf16 per smem row (32 + 8 pad)
#define RSB     (RSTRIDE * 2)          // 80 bytes
#define OFF_AH  0
#define OFF_AL  (GBM * RSB)
#define OFF_BH  (2 * GBM * RSB)
#define OFF_BL  (2 * GBM * RSB + GBN * RSB)
#define STAGE_BYTES (2 * GBM * RSB + 2 * GBN * RSB)  // 61440
#define NSTAGE  3
#define GEMM_SMEM (NSTAGE * STAGE_BYTES)             // 184320

__global__ __launch_bounds__(256, 1) void gemm_bf16x3(
    int M, int N, int K,
    const __nv_bfloat16* __restrict__ Ah, const __nv_bfloat16* __restrict__ Al,
    const __nv_bfloat16* __restrict__ Bh, const __nv_bfloat16* __restrict__ Bl,
    const int* __restrict__ rowlist,
    float* __restrict__ C)
{
    extern __shared__ char smem[];
    __shared__ int srl[GBM];
    const uint32_t sb = smem_to_u32(smem);
    const int tid  = threadIdx.x;
    const int wid  = tid >> 5;
    const int lane = tid & 31;

    const int m0 = blockIdx.y * GBM;
    const int n0 = blockIdx.x * GBN;
    const int iters = K >> 5;

    if (tid < GBM) srl[tid] = rowlist ? rowlist[m0 + tid] : (m0 + tid);
    __syncthreads();

    const int warp_m = (wid & 1) * 64;
    const int warp_n = (wid >> 1) * 64;

    float acc[4][8][4];
    #pragma unroll
    for (int i = 0; i < 4; i++)
        #pragma unroll
        for (int j = 0; j < 8; j++)
            #pragma unroll
            for (int q = 0; q < 4; q++) acc[i][j][q] = 0.0f;

    // tile loader: 3072 16B chunks per stage, 12 per thread
    auto load_stage = [&](int it, int stage) {
        const uint32_t stg = sb + stage * STAGE_BYTES;
        const int k0 = it * GBK;
        #pragma unroll
        for (int i = 0; i < 12; i++) {
            int c = i * 256 + tid;
            const __nv_bfloat16* g;
            uint32_t soff;
            if (c < 1024) {            // A hi/lo: 2 x 128 rows x 4 chunks
                int mat = c >> 9;
                int rk  = c & 511;
                int row = rk >> 2, kc = rk & 3;
                g = (mat ? Al : Ah) + (size_t)srl[row] * K + k0 + kc * 8;
                soff = (mat ? OFF_AL : OFF_AH) + row * RSB + kc * 16;
            } else {                   // B hi/lo: 2 x 256 rows x 4 chunks
                int c2 = c - 1024;
                int mat = c2 >> 10;
                int rk  = c2 & 1023;
                int row = rk >> 2, kc = rk & 3;
                g = (mat ? Bl : Bh) + (size_t)(n0 + row) * K + k0 + kc * 8;
                soff = (mat ? OFF_BL : OFF_BH) + row * RSB + kc * 16;
            }
            cp_async16(stg + soff, g);
        }
    };

    load_stage(0, 0); CP_COMMIT();
    load_stage(1, 1); CP_COMMIT();

    const int a_row  = lane & 15;
    const int a_byte = (lane >> 4) << 4;
    const int b_row  = ((lane >> 4) << 3) + (lane & 7);
    const int b_byte = ((lane >> 3) & 1) << 4;

    #pragma unroll 1
    for (int it = 0; it < iters; ++it) {
        if (it + 1 < iters) { CP_WAIT(1); } else { CP_WAIT(0); }
        __syncthreads();

        if (it + 2 < iters) {
            load_stage(it + 2, (it + 2) % NSTAGE);
            CP_COMMIT();
        }

        const uint32_t stg = sb + (it % NSTAGE) * STAGE_BYTES;
        const uint32_t aARow = stg + (warp_m + a_row) * RSB + a_byte;
        const uint32_t aBRow = stg + (warp_n + b_row) * RSB + b_byte;

        #pragma unroll
        for (int kc = 0; kc < 2; kc++) {
            const uint32_t kb = kc * 32;
            uint32_t ah[4][4], al[4][4], bh[8][2], bl[8][2];
            #pragma unroll
            for (int i = 0; i < 4; i++) {
                ldsm_x4(ah[i][0], ah[i][1], ah[i][2], ah[i][3],
                        aARow + OFF_AH + i * 16 * RSB + kb);
                ldsm_x4(al[i][0], al[i][1], al[i][2], al[i][3],
                        aARow + OFF_AL + i * 16 * RSB + kb);
            }
            #pragma unroll
            for (int jj = 0; jj < 4; jj++) {
                ldsm_x4(bh[2*jj][0], bh[2*jj][1], bh[2*jj+1][0], bh[2*jj+1][1],
                        aBRow + OFF_BH + jj * 16 * RSB + kb);
                ldsm_x4(bl[2*jj][0], bl[2*jj][1], bl[2*jj+1][0], bl[2*jj+1][1],
                        aBRow + OFF_BL + jj * 16 * RSB + kb);
            }
            #pragma unroll
            for (int i = 0; i < 4; i++)
                #pragma unroll
                for (int j = 0; j < 8; j++) {
                    mma16816(acc[i][j], ah[i][0], ah[i][1], ah[i][2], ah[i][3],
                             bh[j][0], bh[j][1]);
                    mma16816(acc[i][j], ah[i][0], ah[i][1], ah[i][2], ah[i][3],
                             bl[j][0], bl[j][1]);
                    mma16816(acc[i][j], al[i][0], al[i][1], al[i][2], al[i][3],
                             bh[j][0], bh[j][1]);
                }
        }
        __syncthreads();
    }

    // epilogue: fragment -> global fp32 (C rows are compact/tile rows)
    const int er = lane >> 2;
    const int ec = (lane & 3) * 2;
    #pragma unroll
    for (int i = 0; i < 4; i++) {
        #pragma unroll
        for (int j = 0; j < 8; j++) {
            int row = m0 + warp_m + i * 16 + er;
            int col = n0 + warp_n + j * 8 + ec;
            float* p0 = C + (size_t)row * N + col;
            float* p1 = C + (size_t)(row + 8) * N + col;
            p0[0] = acc[i][j][0]; p0[1] = acc[i][j][1];
            p1[0] = acc[i][j][2]; p1[1] = acc[i][j][3];
        }
    }
}

// ---------------------------------------------------------------------------
// Fused segment attention. Q gathered from g_q by map; K/V contiguous from
// the compacted g_kv; epilogue writes bf16 hi/lo split directly (feeds the
// output GEMM, no intermediate fp32 buffer).
// ---------------------------------------------------------------------------
__global__ __launch_bounds__(128) void attn_kernel() {
    __shared__ float KV[64][64];     // 16 KB
    __shared__ float Pt[64][128];    // 32 KB

    const int bid = blockIdx.x;
    const int n = bid % NSEG;
    const int h = (bid / NSEG) % NH;
    const int b = bid / (NSEG * NH);
    const int tid = threadIdx.x;

    const int j0   = tid >> 1;
    const int half = (tid & 1) * 32;
    const size_t kvrow = ((size_t)b * 4096 + n * 64 + j0) * (2 * DM);

    // K tile (compact rows, contiguous)
    {
        const float4* src = (const float4*)(g_kv + kvrow + h * DH + half);
        float4* dst = (float4*)&KV[j0][half];
        #pragma unroll
        for (int i = 0; i < 8; i++) dst[i] = src[i];
    }

    float q[DH];
    const int sq = g_map[n * SEG + tid];
    {
        const float4* qp = (const float4*)(g_q +
            ((size_t)(b * S_LEN + sq)) * DM + h * DH);
        #pragma unroll
        for (int i = 0; i < 16; i++) {
            float4 t = qp[i];
            q[4*i] = t.x; q[4*i+1] = t.y; q[4*i+2] = t.z; q[4*i+3] = t.w;
        }
    }
    __syncthreads();

    float mx = -1e30f;
    for (int j = 0; j < 64; j++) {
        const float4* kr = (const float4*)KV[j];
        float s = 0.0f;
        #pragma unroll
        for (int d = 0; d < 16; d++) {
            float4 kk = kr[d];
            s += q[4*d]   * kk.x + q[4*d+1] * kk.y
               + q[4*d+2] * kk.z + q[4*d+3] * kk.w;
        }
        s *= 0.125f;
        mx = fmaxf(mx, s);
        Pt[j][tid] = s;
    }

    float sum = 0.0f;
    for (int j = 0; j < 64; j++) {
        float p = expf(Pt[j][tid] - mx);
        sum += p;
        Pt[j][tid] = p;
    }
    __syncthreads();

    // V tile (same compact row, +DM offset)
    {
        const float4* src = (const float4*)(g_kv + kvrow + DM + h * DH + half);
        float4* dst = (float4*)&KV[j0][half];
        #pragma unroll
        for (int i = 0; i < 8; i++) dst[i] = src[i];
    }
    __syncthreads();

    float4 out[16];
    #pragma unroll
    for (int i = 0; i < 16; i++) out[i] = make_float4(0.f, 0.f, 0.f, 0.f);

    for (int j = 0; j < 64; j++) {
        float p = Pt[j][tid];
        const float4* vr = (const float4*)KV[j];
        #pragma unroll
        for (int d = 0; d < 16; d++) {
            float4 vv = vr[d];
            out[d].x += p * vv.x; out[d].y += p * vv.y;
            out[d].z += p * vv.z; out[d].w += p * vv.w;
        }
    }

    // epilogue: scale + bf16 hi/lo split, written straight to GEMM2 operands
    const float inv = 1.0f / sum;
    const size_t ofs = ((size_t)(b * S_LEN + sq)) * DM + h * DH;
    __nv_bfloat162* hp = (__nv_bfloat162*)(g_ahi + ofs);
    __nv_bfloat162* lp = (__nv_bfloat162*)(g_alo + ofs);
    #pragma unroll
    for (int i = 0; i < 16; i++) {
        float vx = out[i].x * inv, vy = out[i].y * inv;
        float vz = out[i].z * inv, vw = out[i].w * inv;
        __nv_bfloat16 hx = __float2bfloat16_rn(vx);
        __nv_bfloat16 hy = __float2bfloat16_rn(vy);
        __nv_bfloat16 hz = __float2bfloat16_rn(vz);
        __nv_bfloat16 hw = __float2bfloat16_rn(vw);
        hp[2*i]   = __nv_bfloat162(hx, hy);
        hp[2*i+1] = __nv_bfloat162(hz, hw);
        lp[2*i]   = __nv_bfloat162(__float2bfloat16_rn(vx - __bfloat162float(hx)),
                                   __float2bfloat16_rn(vy - __bfloat162float(hy)));
        lp[2*i+1] = __nv_bfloat162(__float2bfloat16_rn(vz - __bfloat162float(hz)),
                                   __float2bfloat16_rn(vw - __bfloat162float(hw)));
    }
}

// ---------------------------------------------------------------------------
// Launch
// ---------------------------------------------------------------------------
extern "C" void kernel_launch(void* const* d_in, const int* in_sizes, int n_in,
                              void* d_out, int out_size)
{
    const float* x    = (const float*)d_in[0];   // [2,8192,1024]
    const float* wqkv = (const float*)d_in[1];   // [1024,3072]
    const float* wout = (const float*)d_in[2];   // [1024,1024]
    float*       out  = (float*)d_out;           // [2,8192,1024]

    float *q_p, *kv_p;
    __nv_bfloat16 *xhi, *xlo, *ahi, *alo, *wqh, *wql, *woh, *wol;
    int *rowkv_p;
    cudaGetSymbolAddress((void**)&q_p,  g_q);
    cudaGetSymbolAddress((void**)&kv_p, g_kv);
    cudaGetSymbolAddress((void**)&xhi, g_xhi);
    cudaGetSymbolAddress((void**)&xlo, g_xlo);
    cudaGetSymbolAddress((void**)&ahi, g_ahi);
    cudaGetSymbolAddress((void**)&alo, g_alo);
    cudaGetSymbolAddress((void**)&wqh, g_wqh);
    cudaGetSymbolAddress((void**)&wql, g_wql);
    cudaGetSymbolAddress((void**)&woh, g_woh);
    cudaGetSymbolAddress((void**)&wol, g_wol);
    cudaGetSymbolAddress((void**)&rowkv_p, g_rowkv);

    static bool attr_set = false;
    if (!attr_set) {
        cudaFuncSetAttribute(gemm_bf16x3,
            cudaFuncAttributeMaxDynamicSharedMemorySize, GEMM_SMEM);
        attr_set = true;
    }

    // 1. maps + operand preparation
    map_kernel<<<(S_LEN + 255) / 256, 256>>>();
    rowkv_kernel<<<(KVROWS + 255) / 256, 256>>>();
    split_kernel<<<(MROWS * DM / 4 + 255) / 256, 256>>>(x, xhi, xlo, MROWS * DM / 4);
    {
        dim3 blk(32, 8);
        transpose_split_kernel<<<dim3(3 * DM / 32, DM / 32), blk>>>(wqkv, wqh, wql, DM, 3 * DM);
        transpose_split_kernel<<<dim3(DM / 32, DM / 32), blk>>>(wout, woh, wol, DM, DM);
    }

    // 2a. Q projection: all rows, N=1024 (W_qkv^T rows [0,1024))
    gemm_bf16x3<<<dim3(DM / GBN, MROWS / GBM), 256, GEMM_SMEM>>>(
        MROWS, DM, DM, xhi, xlo, wqh, wql, nullptr, q_p);

    // 2b. K/V projection: gathered rows (dilated positions only), N=2048
    gemm_bf16x3<<<dim3(2 * DM / GBN, KVROWS / GBM), 256, GEMM_SMEM>>>(
        KVROWS, 2 * DM, DM, xhi, xlo,
        wqh + (size_t)DM * DM, wql + (size_t)DM * DM, rowkv_p, kv_p);

    // 3. segment attention (fp32; writes bf16 split directly)
    attn_kernel<<<B_SZ * NH * NSEG, 128>>>();

    // 4. output projection: [16384,1024] @ [1024,1024]
    gemm_bf16x3<<<dim3(DM / GBN, MROWS / GBM), 256, GEMM_SMEM>>>(
        MROWS, DM, DM, ahi, alo, woh, wol, nullptr, out);
}

// round 5
// speedup vs baseline: 2.8623x; 1.1826x over previous
#include <cuda_runtime.h>
#include <cuda_bf16.h>
#include <cstdint>
#include <math.h>

// Problem constants (fixed by the dataset)
#define S_LEN  8192
#define B_SZ   2
#define DM     1024
#define NH     16
#define DH     64
#define SEG    128
#define NSEG   (S_LEN / SEG)     // 64
#define GRID_G 91                // ceil(sqrt(8192))

#define MROWS  (B_SZ * S_LEN)      // 16384
#define KVROWS (B_SZ * S_LEN / 2)  // 8192 compacted K/V rows

// ---------------------------------------------------------------------------
// Scratch (allocation-free rule: __device__ globals)
// ---------------------------------------------------------------------------
__device__ __nv_bfloat16  g_qhi [MROWS * DM];          // Q bf16 hi [B*S, 1024]
__device__ __nv_bfloat16  g_qlo [MROWS * DM];
__device__ __nv_bfloat16  g_kvhi[KVROWS * 2 * DM];     // compact [K|V] bf16 hi
__device__ __nv_bfloat16  g_kvlo[KVROWS * 2 * DM];
__device__ __nv_bfloat16  g_xhi [MROWS * DM];          // x split hi
__device__ __nv_bfloat16  g_xlo [MROWS * DM];
__device__ __nv_bfloat16  g_ahi [MROWS * DM];          // attn-out split hi
__device__ __nv_bfloat16  g_alo [MROWS * DM];
__device__ __nv_bfloat16  g_wqh [3 * DM * DM];         // W_qkv^T split [3072,1024]
__device__ __nv_bfloat16  g_wql [3 * DM * DM];
__device__ __nv_bfloat16  g_woh [DM * DM];             // W_out^T split [1024,1024]
__device__ __nv_bfloat16  g_wol [DM * DM];
__device__ int            g_rowkv[KVROWS];             // gathered A rows for K/V GEMM

// ---------------------------------------------------------------------------
// PTX helpers (compute_103-safe subset: ldmatrix / mma.sync / cp.async)
// ---------------------------------------------------------------------------
__device__ __forceinline__ uint32_t smem_to_u32(const void* p) {
    uint32_t a;
    asm("{ .reg .u64 t; cvta.to.shared.u64 t, %1; cvt.u32.u64 %0, t; }"
        : "=r"(a) : "l"(p));
    return a;
}
__device__ __forceinline__ void cp_async16(uint32_t saddr, const void* gptr) {
    asm volatile("cp.async.cg.shared.global [%0], [%1], 16;"
                 :: "r"(saddr), "l"(gptr));
}
#define CP_COMMIT() asm volatile("cp.async.commit_group;")
#define CP_WAIT(n)  asm volatile("cp.async.wait_group %0;" :: "n"(n))

__device__ __forceinline__ void ldsm_x4(uint32_t& r0, uint32_t& r1,
                                        uint32_t& r2, uint32_t& r3,
                                        uint32_t addr) {
    asm volatile("ldmatrix.sync.aligned.m8n8.x4.shared.b16 {%0,%1,%2,%3}, [%4];"
                 : "=r"(r0), "=r"(r1), "=r"(r2), "=r"(r3) : "r"(addr));
}
__device__ __forceinline__ void ldsm_x4_t(uint32_t& r0, uint32_t& r1,
                                          uint32_t& r2, uint32_t& r3,
                                          uint32_t addr) {
    asm volatile("ldmatrix.sync.aligned.m8n8.x4.trans.shared.b16 {%0,%1,%2,%3}, [%4];"
                 : "=r"(r0), "=r"(r1), "=r"(r2), "=r"(r3) : "r"(addr));
}
__device__ __forceinline__ void mma16816(float* c,
                                         uint32_t a0, uint32_t a1,
                                         uint32_t a2, uint32_t a3,
                                         uint32_t b0, uint32_t b1) {
    asm volatile(
        "mma.sync.aligned.m16n8k16.row.col.f32.bf16.bf16.f32 "
        "{%0,%1,%2,%3}, {%4,%5,%6,%7}, {%8,%9}, {%0,%1,%2,%3};"
        : "+f"(c[0]), "+f"(c[1]), "+f"(c[2]), "+f"(c[3])
        : "r"(a0), "r"(a1), "r"(a2), "r"(a3), "r"(b0), "r"(b1));
}

__device__ __forceinline__ uint32_t pack_bf16hi(float a, float b) {
    __nv_bfloat162 t(__float2bfloat16_rn(a), __float2bfloat16_rn(b));
    return *(uint32_t*)&t;
}
// hi/lo split pack: hi = bf16(v), lo = bf16(v - hi)
__device__ __forceinline__ void pack_split(float a, float b,
                                           uint32_t& hi, uint32_t& lo) {
    __nv_bfloat16 ha = __float2bfloat16_rn(a);
    __nv_bfloat16 hb = __float2bfloat16_rn(b);
    __nv_bfloat162 th(ha, hb);
    __nv_bfloat162 tl(__float2bfloat16_rn(a - __bfloat162float(ha)),
                      __float2bfloat16_rn(b - __bfloat162float(hb)));
    hi = *(uint32_t*)&th;
    lo = *(uint32_t*)&tl;
}

// ---------------------------------------------------------------------------
// Closed-form boustrophedon map
// ---------------------------------------------------------------------------
__device__ __forceinline__ int hmap(int lp) {
    int r = lp / GRID_G;
    int c = lp % GRID_G;
    int vr = min(GRID_G, S_LEN - r * GRID_G);
    return ((r & 1) == 0) ? (r * GRID_G + c) : (r * GRID_G + vr - 1 - c);
}

// Row list for the gathered K/V GEMM
__global__ void rowkv_kernel() {
    int i = blockIdx.x * 256 + threadIdx.x;
    if (i >= KVROWS) return;
    int b = i >> 12;
    int r = i & 4095;
    int n = r >> 6, j = r & 63;
    g_rowkv[i] = b * S_LEN + hmap(n * SEG + 2 * j);
}

// ---------------------------------------------------------------------------
// fp32 -> (bf16 hi, bf16 lo) elementwise split
// ---------------------------------------------------------------------------
__global__ __launch_bounds__(256) void split_kernel(
    const float* __restrict__ src, __nv_bfloat16* __restrict__ hi,
    __nv_bfloat16* __restrict__ lo, int n4)
{
    int i = blockIdx.x * 256 + threadIdx.x;
    if (i >= n4) return;
    float4 v = ((const float4*)src)[i];
    uint32_t h0, l0, h1, l1;
    pack_split(v.x, v.y, h0, l0);
    pack_split(v.z, v.w, h1, l1);
    ((uint32_t*)hi)[2 * i] = h0; ((uint32_t*)hi)[2 * i + 1] = h1;
    ((uint32_t*)lo)[2 * i] = l0; ((uint32_t*)lo)[2 * i + 1] = l1;
}

// ---------------------------------------------------------------------------
// W [K,N] fp32 -> W^T [N,K] bf16 hi/lo (tiled transpose + split)
// ---------------------------------------------------------------------------
__global__ __launch_bounds__(256) void transpose_split_kernel(
    const float* __restrict__ W, __nv_bfloat16* __restrict__ Thi,
    __nv_bfloat16* __restrict__ Tlo, int K, int N)
{
    __shared__ float t[32][33];
    int n0 = blockIdx.x * 32, k0 = blockIdx.y * 32;
    int tx = threadIdx.x, ty = threadIdx.y;    // block (32, 8)
    #pragma unroll
    for (int i = 0; i < 4; i++)
        t[ty + 8 * i][tx] = W[(size_t)(k0 + ty + 8 * i) * N + n0 + tx];
    __syncthreads();
    #pragma unroll
    for (int i = 0; i < 4; i++) {
        float v = t[tx][ty + 8 * i];
        __nv_bfloat16 h = __float2bfloat16_rn(v);
        size_t o = (size_t)(n0 + ty + 8 * i) * K + k0 + tx;
        Thi[o] = h;
        Tlo[o] = __float2bfloat16_rn(v - __bfloat162float(h));
    }
}

// ---------------------------------------------------------------------------
// HMMA bf16x3-split GEMM with optional gathered A rows and optional bf16
// split output.  BM=128, BN=256, BK=32, 256 threads, 3-stage cp.async.
// ---------------------------------------------------------------------------
#define GBM 128
#define GBN 256
#define GBK 32
#define RSTRIDE 40                     // bf16 per smem row (32 + 8 pad)
#define RSB     (RSTRIDE * 2)          // 80 bytes
#define OFF_AH  0
#define OFF_AL  (GBM * RSB)
#define OFF_BH  (2 * GBM * RSB)
#define OFF_BL  (2 * GBM * RSB + GBN * RSB)
#define STAGE_BYTES (2 * GBM * RSB + 2 * GBN * RSB)  // 61440
#define NSTAGE  3
#define GEMM_SMEM (NSTAGE * STAGE_BYTES)             // 184320

__global__ __launch_bounds__(256, 1) void gemm_bf16x3(
    int M, int N, int K,
    const __nv_bfloat16* __restrict__ Ah, const __nv_bfloat16* __restrict__ Al,
    const __nv_bfloat16* __restrict__ Bh, const __nv_bfloat16* __restrict__ Bl,
    const int* __restrict__ rowlist,
    float* __restrict__ C,
    __nv_bfloat16* __restrict__ Chi, __nv_bfloat16* __restrict__ Clo)
{
    extern __shared__ char smem[];
    __shared__ int srl[GBM];
    const uint32_t sb = smem_to_u32(smem);
    const int tid  = threadIdx.x;
    const int wid  = tid >> 5;
    const int lane = tid & 31;

    const int m0 = blockIdx.y * GBM;
    const int n0 = blockIdx.x * GBN;
    const int iters = K >> 5;

    if (tid < GBM) srl[tid] = rowlist ? rowlist[m0 + tid] : (m0 + tid);
    __syncthreads();

    const int warp_m = (wid & 1) * 64;
    const int warp_n = (wid >> 1) * 64;

    float acc[4][8][4];
    #pragma unroll
    for (int i = 0; i < 4; i++)
        #pragma unroll
        for (int j = 0; j < 8; j++)
            #pragma unroll
            for (int q = 0; q < 4; q++) acc[i][j][q] = 0.0f;

    auto load_stage = [&](int it, int stage) {
        const uint32_t stg = sb + stage * STAGE_BYTES;
        const int k0 = it * GBK;
        #pragma unroll
        for (int i = 0; i < 12; i++) {
            int c = i * 256 + tid;
            const __nv_bfloat16* g;
            uint32_t soff;
            if (c < 1024) {
                int mat = c >> 9;
                int rk  = c & 511;
                int row = rk >> 2, kc = rk & 3;
                g = (mat ? Al : Ah) + (size_t)srl[row] * K + k0 + kc * 8;
                soff = (mat ? OFF_AL : OFF_AH) + row * RSB + kc * 16;
            } else {
                int c2 = c - 1024;
                int mat = c2 >> 10;
                int rk  = c2 & 1023;
                int row = rk >> 2, kc = rk & 3;
                g = (mat ? Bl : Bh) + (size_t)(n0 + row) * K + k0 + kc * 8;
                soff = (mat ? OFF_BL : OFF_BH) + row * RSB + kc * 16;
            }
            cp_async16(stg + soff, g);
        }
    };

    load_stage(0, 0); CP_COMMIT();
    load_stage(1, 1); CP_COMMIT();

    const int a_row  = lane & 15;
    const int a_byte = (lane >> 4) << 4;
    const int b_row  = ((lane >> 4) << 3) + (lane & 7);
    const int b_byte = ((lane >> 3) & 1) << 4;

    #pragma unroll 1
    for (int it = 0; it < iters; ++it) {
        if (it + 1 < iters) { CP_WAIT(1); } else { CP_WAIT(0); }
        __syncthreads();

        if (it + 2 < iters) {
            load_stage(it + 2, (it + 2) % NSTAGE);
            CP_COMMIT();
        }

        const uint32_t stg = sb + (it % NSTAGE) * STAGE_BYTES;
        const uint32_t aARow = stg + (warp_m + a_row) * RSB + a_byte;
        const uint32_t aBRow = stg + (warp_n + b_row) * RSB + b_byte;

        #pragma unroll
        for (int kc = 0; kc < 2; kc++) {
            const uint32_t kb = kc * 32;
            uint32_t ah[4][4], al[4][4], bh[8][2], bl[8][2];
            #pragma unroll
            for (int i = 0; i < 4; i++) {
                ldsm_x4(ah[i][0], ah[i][1], ah[i][2], ah[i][3],
                        aARow + OFF_AH + i * 16 * RSB + kb);
                ldsm_x4(al[i][0], al[i][1], al[i][2], al[i][3],
                        aARow + OFF_AL + i * 16 * RSB + kb);
            }
            #pragma unroll
            for (int jj = 0; jj < 4; jj++) {
                ldsm_x4(bh[2*jj][0], bh[2*jj][1], bh[2*jj+1][0], bh[2*jj+1][1],
                        aBRow + OFF_BH + jj * 16 * RSB + kb);
                ldsm_x4(bl[2*jj][0], bl[2*jj][1], bl[2*jj+1][0], bl[2*jj+1][1],
                        aBRow + OFF_BL + jj * 16 * RSB + kb);
            }
            #pragma unroll
            for (int i = 0; i < 4; i++)
                #pragma unroll
                for (int j = 0; j < 8; j++) {
                    mma16816(acc[i][j], ah[i][0], ah[i][1], ah[i][2], ah[i][3],
                             bh[j][0], bh[j][1]);
                    mma16816(acc[i][j], ah[i][0], ah[i][1], ah[i][2], ah[i][3],
                             bl[j][0], bl[j][1]);
                    mma16816(acc[i][j], al[i][0], al[i][1], al[i][2], al[i][3],
                             bh[j][0], bh[j][1]);
                }
        }
        // no trailing barrier: stage it%3 is only overwritten by loads issued
        // after the NEXT iteration's top barrier (3-stage rotation).
    }

    // epilogue
    const int er = lane >> 2;
    const int ec = (lane & 3) * 2;
    if (Chi) {
        #pragma unroll
        for (int i = 0; i < 4; i++) {
            #pragma unroll
            for (int j = 0; j < 8; j++) {
                int row = m0 + warp_m + i * 16 + er;
                int col = n0 + warp_n + j * 8 + ec;
                uint32_t h0, l0, h1, l1;
                pack_split(acc[i][j][0], acc[i][j][1], h0, l0);
                pack_split(acc[i][j][2], acc[i][j][3], h1, l1);
                *(uint32_t*)(Chi + (size_t)row * N + col)       = h0;
                *(uint32_t*)(Clo + (size_t)row * N + col)       = l0;
                *(uint32_t*)(Chi + (size_t)(row + 8) * N + col) = h1;
                *(uint32_t*)(Clo + (size_t)(row + 8) * N + col) = l1;
            }
        }
    } else {
        #pragma unroll
        for (int i = 0; i < 4; i++) {
            #pragma unroll
            for (int j = 0; j < 8; j++) {
                int row = m0 + warp_m + i * 16 + er;
                int col = n0 + warp_n + j * 8 + ec;
                float* p0 = C + (size_t)row * N + col;
                float* p1 = C + (size_t)(row + 8) * N + col;
                p0[0] = acc[i][j][0]; p0[1] = acc[i][j][1];
                p1[0] = acc[i][j][2]; p1[1] = acc[i][j][3];
            }
        }
    }
}

// ---------------------------------------------------------------------------
// Tensor-core segment attention (bf16x3 HMMA, softmax in fragments).
// One block per (b, h, seg): 128 threads = 4 warps, 32 q-rows per warp.
// smem: swizzled bf16 tiles Qh/Ql[128x64], Kh/Kl[64x64], Vh/Vl[64x64] = 64KB.
// ---------------------------------------------------------------------------
#define ASM_QH 0
#define ASM_QL 16384
#define ASM_KH 32768
#define ASM_KL 40960
#define ASM_VH 49152
#define ASM_VL 57344
#define ATTN_SMEM 65536
// swizzled address within a tile: row stride 128B, 16B chunks XOR'd by row&7
#define SWIZ(base, row, ch) ((base) + (row) * 128 + ((((ch) ^ ((row) & 7))) << 4))

__global__ __launch_bounds__(128) void attn_kernel() {
    extern __shared__ char asmem[];
    const uint32_t sb = smem_to_u32(asmem);

    const int bid = blockIdx.x;
    const int n = bid % NSEG;
    const int h = (bid / NSEG) % NH;
    const int b = bid / (NSEG * NH);
    const int tid = threadIdx.x;
    const int wid = tid >> 5;
    const int lane = tid & 31;
    const int warp_m = wid * 32;

    // ---- load Q (hi/lo): 2048 16B chunks ----
    #pragma unroll
    for (int i = 0; i < 16; i++) {
        int c = i * 128 + tid;
        int mat = c >> 10;              // 0=hi 1=lo
        int rc  = c & 1023;
        int row = rc >> 3, ch = rc & 7;
        int sq = hmap(n * SEG + row);
        const __nv_bfloat16* g = (mat ? g_qlo : g_qhi) +
            ((size_t)(b * S_LEN + sq)) * DM + h * DH + ch * 8;
        cp_async16(SWIZ(sb + (mat ? ASM_QL : ASM_QH), row, ch), g);
    }
    // ---- load K and V (hi/lo): 2048 16B chunks ----
    #pragma unroll
    for (int i = 0; i < 16; i++) {
        int c = i * 128 + tid;
        int kv  = c >> 10;              // 0=K 1=V
        int mat = (c >> 9) & 1;         // 0=hi 1=lo
        int rc  = c & 511;
        int row = rc >> 3, ch = rc & 7;
        size_t go = ((size_t)b * 4096 + n * 64 + row) * (2 * DM)
                  + (size_t)kv * DM + h * DH + ch * 8;
        const __nv_bfloat16* g = (mat ? g_kvlo : g_kvhi) + go;
        uint32_t base = kv ? (mat ? ASM_VL : ASM_VH) : (mat ? ASM_KL : ASM_KH);
        cp_async16(SWIZ(sb + base, row, ch), g);
    }
    CP_COMMIT();
    CP_WAIT(0);
    __syncthreads();

    // ---- scores: S = Q @ K^T  (bf16x3) ----
    float acc_s[2][8][4];
    #pragma unroll
    for (int i = 0; i < 2; i++)
        #pragma unroll
        for (int j = 0; j < 8; j++)
            #pragma unroll
            for (int q = 0; q < 4; q++) acc_s[i][j][q] = 0.0f;

    const int a_r  = lane & 15;
    const int a_c  = lane >> 4;             // chunk offset 0/1
    const int b_r  = ((lane >> 4) << 3) + (lane & 7);
    const int b_c  = (lane >> 3) & 1;

    #pragma unroll
    for (int t = 0; t < 4; t++) {
        uint32_t qh[2][4], ql[2][4], kh[8][2], kl[8][2];
        #pragma unroll
        for (int i = 0; i < 2; i++) {
            int row = warp_m + i * 16 + a_r;
            int ch = 2 * t + a_c;
            ldsm_x4(qh[i][0], qh[i][1], qh[i][2], qh[i][3],
                    SWIZ(sb + ASM_QH, row, ch));
            ldsm_x4(ql[i][0], ql[i][1], ql[i][2], ql[i][3],
                    SWIZ(sb + ASM_QL, row, ch));
        }
        #pragma unroll
        for (int jj = 0; jj < 4; jj++) {
            int row = jj * 16 + b_r;
            int ch = 2 * t + b_c;
            ldsm_x4(kh[2*jj][0], kh[2*jj][1], kh[2*jj+1][0], kh[2*jj+1][1],
                    SWIZ(sb + ASM_KH, row, ch));
            ldsm_x4(kl[2*jj][0], kl[2*jj][1], kl[2*jj+1][0], kl[2*jj+1][1],
                    SWIZ(sb + ASM_KL, row, ch));
        }
        #pragma unroll
        for (int i = 0; i < 2; i++)
            #pragma unroll
            for (int j = 0; j < 8; j++) {
                mma16816(acc_s[i][j], qh[i][0], qh[i][1], qh[i][2], qh[i][3],
                         kh[j][0], kh[j][1]);
                mma16816(acc_s[i][j], qh[i][0], qh[i][1], qh[i][2], qh[i][3],
                         kl[j][0], kl[j][1]);
                mma16816(acc_s[i][j], ql[i][0], ql[i][1], ql[i][2], ql[i][3],
                         kh[j][0], kh[j][1]);
            }
    }

    // ---- softmax over 64 cols, per fragment row (quad shfl reduce) ----
    #pragma unroll
    for (int i = 0; i < 2; i++) {
        #pragma unroll
        for (int half = 0; half < 2; half++) {
            float mx = -1e30f;
            #pragma unroll
            for (int j = 0; j < 8; j++) {
                mx = fmaxf(mx, acc_s[i][j][half*2]);
                mx = fmaxf(mx, acc_s[i][j][half*2+1]);
            }
            mx = fmaxf(mx, __shfl_xor_sync(0xffffffffu, mx, 1));
            mx = fmaxf(mx, __shfl_xor_sync(0xffffffffu, mx, 2));
            float sum = 0.0f;
            #pragma unroll
            for (int j = 0; j < 8; j++) {
                float p0 = expf((acc_s[i][j][half*2]   - mx) * 0.125f);
                float p1 = expf((acc_s[i][j][half*2+1] - mx) * 0.125f);
                acc_s[i][j][half*2]   = p0;
                acc_s[i][j][half*2+1] = p1;
                sum += p0 + p1;
            }
            sum += __shfl_xor_sync(0xffffffffu, sum, 1);
            sum += __shfl_xor_sync(0xffffffffu, sum, 2);
            float inv = 1.0f / sum;
            #pragma unroll
            for (int j = 0; j < 8; j++) {
                acc_s[i][j][half*2]   *= inv;
                acc_s[i][j][half*2+1] *= inv;
            }
        }
    }

    // ---- O = P @ V  (P in frags, V^T frags via ldmatrix.trans) ----
    float acc_o[2][8][4];
    #pragma unroll
    for (int i = 0; i < 2; i++)
        #pragma unroll
        for (int j = 0; j < 8; j++)
            #pragma unroll
            for (int q = 0; q < 4; q++) acc_o[i][j][q] = 0.0f;

    #pragma unroll
    for (int t = 0; t < 4; t++) {
        // repack P C-frags (n-tiles 2t, 2t+1) into A-frags (k-step t), hi/lo
        uint32_t ph[2][4], pl[2][4];
        #pragma unroll
        for (int i = 0; i < 2; i++) {
            pack_split(acc_s[i][2*t][0],   acc_s[i][2*t][1],   ph[i][0], pl[i][0]);
            pack_split(acc_s[i][2*t][2],   acc_s[i][2*t][3],   ph[i][1], pl[i][1]);
            pack_split(acc_s[i][2*t+1][0], acc_s[i][2*t+1][1], ph[i][2], pl[i][2]);
            pack_split(acc_s[i][2*t+1][2], acc_s[i][2*t+1][3], ph[i][3], pl[i][3]);
        }
        // V^T B-frags: trans loads, rows = k (j), chunks = d
        uint32_t vh[8][2], vl[8][2];
        #pragma unroll
        for (int jj = 0; jj < 4; jj++) {
            int row = t * 16 + (lane & 15);
            int ch = jj * 2 + (lane >> 4);
            ldsm_x4_t(vh[2*jj][0], vh[2*jj][1], vh[2*jj+1][0], vh[2*jj+1][1],
                      SWIZ(sb + ASM_VH, row, ch));
            ldsm_x4_t(vl[2*jj][0], vl[2*jj][1], vl[2*jj+1][0], vl[2*jj+1][1],
                      SWIZ(sb + ASM_VL, row, ch));
        }
        #pragma unroll
        for (int i = 0; i < 2; i++)
            #pragma unroll
            for (int nd = 0; nd < 8; nd++) {
                mma16816(acc_o[i][nd], ph[i][0], ph[i][1], ph[i][2], ph[i][3],
                         vh[nd][0], vh[nd][1]);
                mma16816(acc_o[i][nd], ph[i][0], ph[i][1], ph[i][2], ph[i][3],
                         vl[nd][0], vl[nd][1]);
                mma16816(acc_o[i][nd], pl[i][0], pl[i][1], pl[i][2], pl[i][3],
                         vh[nd][0], vh[nd][1]);
            }
    }

    // ---- epilogue: scatter rows back by map, write bf16 hi/lo split ----
    const int er = lane >> 2;
    const int ec = (lane & 3) * 2;
    #pragma unroll
    for (int i = 0; i < 2; i++) {
        #pragma unroll
        for (int half = 0; half < 2; half++) {
            int rowl = warp_m + i * 16 + er + half * 8;
            int sq = hmap(n * SEG + rowl);
            size_t gr = ((size_t)(b * S_LEN + sq)) * DM + h * DH;
            #pragma unroll
            for (int nd = 0; nd < 8; nd++) {
                uint32_t hi, lo;
                pack_split(acc_o[i][nd][half*2], acc_o[i][nd][half*2+1], hi, lo);
                *(uint32_t*)(g_ahi + gr + nd * 8 + ec) = hi;
                *(uint32_t*)(g_alo + gr + nd * 8 + ec) = lo;
            }
        }
    }
}

// ---------------------------------------------------------------------------
// Launch
// ---------------------------------------------------------------------------
extern "C" void kernel_launch(void* const* d_in, const int* in_sizes, int n_in,
                              void* d_out, int out_size)
{
    const float* x    = (const float*)d_in[0];   // [2,8192,1024]
    const float* wqkv = (const float*)d_in[1];   // [1024,3072]
    const float* wout = (const float*)d_in[2];   // [1024,1024]
    float*       out  = (float*)d_out;           // [2,8192,1024]

    __nv_bfloat16 *qhi, *qlo, *kvhi, *kvlo, *xhi, *xlo, *ahi, *alo;
    __nv_bfloat16 *wqh, *wql, *woh, *wol;
    int *rowkv_p;
    cudaGetSymbolAddress((void**)&qhi,  g_qhi);
    cudaGetSymbolAddress((void**)&qlo,  g_qlo);
    cudaGetSymbolAddress((void**)&kvhi, g_kvhi);
    cudaGetSymbolAddress((void**)&kvlo, g_kvlo);
    cudaGetSymbolAddress((void**)&xhi, g_xhi);
    cudaGetSymbolAddress((void**)&xlo, g_xlo);
    cudaGetSymbolAddress((void**)&ahi, g_ahi);
    cudaGetSymbolAddress((void**)&alo, g_alo);
    cudaGetSymbolAddress((void**)&wqh, g_wqh);
    cudaGetSymbolAddress((void**)&wql, g_wql);
    cudaGetSymbolAddress((void**)&woh, g_woh);
    cudaGetSymbolAddress((void**)&wol, g_wol);
    cudaGetSymbolAddress((void**)&rowkv_p, g_rowkv);

    static bool attr_set = false;
    if (!attr_set) {
        cudaFuncSetAttribute(gemm_bf16x3,
            cudaFuncAttributeMaxDynamicSharedMemorySize, GEMM_SMEM);
        cudaFuncSetAttribute(attn_kernel,
            cudaFuncAttributeMaxDynamicSharedMemorySize, ATTN_SMEM);
        attr_set = true;
    }

    // 1. prep
    rowkv_kernel<<<(KVROWS + 255) / 256, 256>>>();
    split_kernel<<<(MROWS * DM / 4 + 255) / 256, 256>>>(x, xhi, xlo, MROWS * DM / 4);
    {
        dim3 blk(32, 8);
        transpose_split_kernel<<<dim3(3 * DM / 32, DM / 32), blk>>>(wqkv, wqh, wql, DM, 3 * DM);
        transpose_split_kernel<<<dim3(DM / 32, DM / 32), blk>>>(wout, woh, wol, DM, DM);
    }

    // 2a. Q projection -> bf16 split
    gemm_bf16x3<<<dim3(DM / GBN, MROWS / GBM), 256, GEMM_SMEM>>>(
        MROWS, DM, DM, xhi, xlo, wqh, wql, nullptr, nullptr, qhi, qlo);

    // 2b. K/V projection (gathered dilated rows) -> bf16 split
    gemm_bf16x3<<<dim3(2 * DM / GBN, KVROWS / GBM), 256, GEMM_SMEM>>>(
        KVROWS, 2 * DM, DM, xhi, xlo,
        wqh + (size_t)DM * DM, wql + (size_t)DM * DM, rowkv_p,
        nullptr, kvhi, kvlo);

    // 3. tensor-core segment attention -> bf16 split
    attn_kernel<<<B_SZ * NH * NSEG, 128, ATTN_SMEM>>>();

    // 4. output projection -> fp32 final
    gemm_bf16x3<<<dim3(DM / GBN, MROWS / GBM), 256, GEMM_SMEM>>>(
        MROWS, DM, DM, ahi, alo, woh, wol, nullptr, out, nullptr, nullptr);
}

// round 6
// speedup vs baseline: 4.0826x; 1.4263x over previous
#include <cuda_runtime.h>
#include <cuda_fp16.h>
#include <cstdint>
#include <math.h>

// Problem constants (fixed by the dataset)
#define S_LEN  8192
#define B_SZ   2
#define DM     1024
#define NH     16
#define DH     64
#define SEG    128
#define NSEG   (S_LEN / SEG)     // 64
#define GRID_G 91                // ceil(sqrt(8192))

#define MROWS  (B_SZ * S_LEN)      // 16384
#define KVROWS (B_SZ * S_LEN / 2)  // 8192 compacted K/V rows

// ---------------------------------------------------------------------------
// Scratch (allocation-free rule: __device__ globals)
// ---------------------------------------------------------------------------
__device__ __half  g_xhi [MROWS * DM];          // x fp16 hi (A-side GEMM1)
__device__ __half  g_xlo [MROWS * DM];          // x fp16 lo
__device__ __half  g_qhi [MROWS * DM];          // Q fp16 hi (A-side scores)
__device__ __half  g_qlo [MROWS * DM];
__device__ __half  g_kv  [KVROWS * 2 * DM];     // compact [K|V] fp16 (B-side)
__device__ __half  g_ahi [MROWS * DM];          // attn-out fp16 hi (A-side out)
__device__ __half  g_alo [MROWS * DM];
__device__ __half  g_wq  [3 * DM * DM];         // W_qkv^T fp16 [3072,1024]
__device__ __half  g_wo  [DM * DM];             // W_out^T fp16 [1024,1024]
__device__ int     g_rowkv[KVROWS];             // gathered A rows for K/V GEMM

// ---------------------------------------------------------------------------
// PTX helpers (compute_103-safe subset: ldmatrix / mma.sync / cp.async)
// ---------------------------------------------------------------------------
__device__ __forceinline__ uint32_t smem_to_u32(const void* p) {
    uint32_t a;
    asm("{ .reg .u64 t; cvta.to.shared.u64 t, %1; cvt.u32.u64 %0, t; }"
        : "=r"(a) : "l"(p));
    return a;
}
__device__ __forceinline__ void cp_async16(uint32_t saddr, const void* gptr) {
    asm volatile("cp.async.cg.shared.global [%0], [%1], 16;"
                 :: "r"(saddr), "l"(gptr));
}
#define CP_COMMIT() asm volatile("cp.async.commit_group;")
#define CP_WAIT(n)  asm volatile("cp.async.wait_group %0;" :: "n"(n))

__device__ __forceinline__ void ldsm_x4(uint32_t& r0, uint32_t& r1,
                                        uint32_t& r2, uint32_t& r3,
                                        uint32_t addr) {
    asm volatile("ldmatrix.sync.aligned.m8n8.x4.shared.b16 {%0,%1,%2,%3}, [%4];"
                 : "=r"(r0), "=r"(r1), "=r"(r2), "=r"(r3) : "r"(addr));
}
__device__ __forceinline__ void ldsm_x4_t(uint32_t& r0, uint32_t& r1,
                                          uint32_t& r2, uint32_t& r3,
                                          uint32_t addr) {
    asm volatile("ldmatrix.sync.aligned.m8n8.x4.trans.shared.b16 {%0,%1,%2,%3}, [%4];"
                 : "=r"(r0), "=r"(r1), "=r"(r2), "=r"(r3) : "r"(addr));
}
__device__ __forceinline__ void mma16816(float* c,
                                         uint32_t a0, uint32_t a1,
                                         uint32_t a2, uint32_t a3,
                                         uint32_t b0, uint32_t b1) {
    asm volatile(
        "mma.sync.aligned.m16n8k16.row.col.f32.f16.f16.f32 "
        "{%0,%1,%2,%3}, {%4,%5,%6,%7}, {%8,%9}, {%0,%1,%2,%3};"
        : "+f"(c[0]), "+f"(c[1]), "+f"(c[2]), "+f"(c[3])
        : "r"(a0), "r"(a1), "r"(a2), "r"(a3), "r"(b0), "r"(b1));
}

// fp16 2x packs
__device__ __forceinline__ uint32_t pack_h2(float a, float b) {
    __half2 t = __halves2half2(__float2half_rn(a), __float2half_rn(b));
    return *(uint32_t*)&t;
}
// hi/lo split pack: hi = fp16(v), lo = fp16(v - hi)
__device__ __forceinline__ void pack_split_h(float a, float b,
                                             uint32_t& hi, uint32_t& lo) {
    __half ha = __float2half_rn(a);
    __half hb = __float2half_rn(b);
    __half2 th = __halves2half2(ha, hb);
    __half2 tl = __halves2half2(__float2half_rn(a - __half2float(ha)),
                                __float2half_rn(b - __half2float(hb)));
    hi = *(uint32_t*)&th;
    lo = *(uint32_t*)&tl;
}

// ---------------------------------------------------------------------------
// Closed-form boustrophedon map
// ---------------------------------------------------------------------------
__device__ __forceinline__ int hmap(int lp) {
    int r = lp / GRID_G;
    int c = lp % GRID_G;
    int vr = min(GRID_G, S_LEN - r * GRID_G);
    return ((r & 1) == 0) ? (r * GRID_G + c) : (r * GRID_G + vr - 1 - c);
}

// Row list for the gathered K/V GEMM
__global__ void rowkv_kernel() {
    int i = blockIdx.x * 256 + threadIdx.x;
    if (i >= KVROWS) return;
    int b = i >> 12;
    int r = i & 4095;
    int n = r >> 6, j = r & 63;
    g_rowkv[i] = b * S_LEN + hmap(n * SEG + 2 * j);
}

// ---------------------------------------------------------------------------
// fp32 -> (fp16 hi, fp16 lo) elementwise split
// ---------------------------------------------------------------------------
__global__ __launch_bounds__(256) void split_kernel(
    const float* __restrict__ src, __half* __restrict__ hi,
    __half* __restrict__ lo, int n4)
{
    int i = blockIdx.x * 256 + threadIdx.x;
    if (i >= n4) return;
    float4 v = ((const float4*)src)[i];
    uint32_t h0, l0, h1, l1;
    pack_split_h(v.x, v.y, h0, l0);
    pack_split_h(v.z, v.w, h1, l1);
    ((uint32_t*)hi)[2 * i] = h0; ((uint32_t*)hi)[2 * i + 1] = h1;
    ((uint32_t*)lo)[2 * i] = l0; ((uint32_t*)lo)[2 * i + 1] = l1;
}

// ---------------------------------------------------------------------------
// W [K,N] fp32 -> W^T [N,K] fp16 (tiled transpose)
// ---------------------------------------------------------------------------
__global__ __launch_bounds__(256) void transpose_h_kernel(
    const float* __restrict__ W, __half* __restrict__ T, int K, int N)
{
    __shared__ float t[32][33];
    int n0 = blockIdx.x * 32, k0 = blockIdx.y * 32;
    int tx = threadIdx.x, ty = threadIdx.y;    // block (32, 8)
    #pragma unroll
    for (int i = 0; i < 4; i++)
        t[ty + 8 * i][tx] = W[(size_t)(k0 + ty + 8 * i) * N + n0 + tx];
    __syncthreads();
    #pragma unroll
    for (int i = 0; i < 4; i++) {
        size_t o = (size_t)(n0 + ty + 8 * i) * K + k0 + tx;
        T[o] = __float2half_rn(t[tx][ty + 8 * i]);
    }
}

// ---------------------------------------------------------------------------
// HMMA fp16x2-split GEMM: C[M,N] = (Ah+Al)[rows][K] @ B[N,K]^T, fp32 acc.
// A-side exact (fp16 hi+lo), B-side single fp16. 2 MMAs per product.
// BM=128, BN=256, BK=32, 256 threads, 3-stage cp.async.
// Output modes: fp32 C, fp16 split (Chi+Clo), or fp16 single (Chi).
// ---------------------------------------------------------------------------
#define GBM 128
#define GBN 256
#define GBK 32
#define RSB 80                         // 32 fp16 + 8 pad = 80 bytes/row
#define OFF_AH  0
#define OFF_AL  (GBM * RSB)            // 10240
#define OFF_B   (2 * GBM * RSB)        // 20480
#define STAGE_BYTES (2 * GBM * RSB + GBN * RSB)  // 40960
#define NSTAGE  3
#define GEMM_SMEM (NSTAGE * STAGE_BYTES)         // 122880

__global__ __launch_bounds__(256, 1) void gemm_fp16x2(
    int M, int N, int K,
    const __half* __restrict__ Ah, const __half* __restrict__ Al,
    const __half* __restrict__ B,
    const int* __restrict__ rowlist,
    float* __restrict__ C,
    __half* __restrict__ Chi, __half* __restrict__ Clo)
{
    extern __shared__ char smem[];
    __shared__ int srl[GBM];
    const uint32_t sb = smem_to_u32(smem);
    const int tid  = threadIdx.x;
    const int wid  = tid >> 5;
    const int lane = tid & 31;

    const int m0 = blockIdx.y * GBM;
    const int n0 = blockIdx.x * GBN;
    const int iters = K >> 5;

    if (tid < GBM) srl[tid] = rowlist ? rowlist[m0 + tid] : (m0 + tid);
    __syncthreads();

    const int warp_m = (wid & 1) * 64;
    const int warp_n = (wid >> 1) * 64;

    float acc[4][8][4];
    #pragma unroll
    for (int i = 0; i < 4; i++)
        #pragma unroll
        for (int j = 0; j < 8; j++)
            #pragma unroll
            for (int q = 0; q < 4; q++) acc[i][j][q] = 0.0f;

    // 2048 16B chunks per stage, 8 per thread
    auto load_stage = [&](int it, int stage) {
        const uint32_t stg = sb + stage * STAGE_BYTES;
        const int k0 = it * GBK;
        #pragma unroll
        for (int i = 0; i < 8; i++) {
            int c = i * 256 + tid;
            const __half* g;
            uint32_t soff;
            if (c < 1024) {            // A hi/lo: 2 x 128 rows x 4 chunks
                int mat = c >> 9;
                int rk  = c & 511;
                int row = rk >> 2, kc = rk & 3;
                g = (mat ? Al : Ah) + (size_t)srl[row] * K + k0 + kc * 8;
                soff = (mat ? OFF_AL : OFF_AH) + row * RSB + kc * 16;
            } else {                   // B: 256 rows x 4 chunks
                int c2 = c - 1024;
                int row = c2 >> 2, kc = c2 & 3;
                g = B + (size_t)(n0 + row) * K + k0 + kc * 8;
                soff = OFF_B + row * RSB + kc * 16;
            }
            cp_async16(stg + soff, g);
        }
    };

    load_stage(0, 0); CP_COMMIT();
    load_stage(1, 1); CP_COMMIT();

    const int a_row  = lane & 15;
    const int a_byte = (lane >> 4) << 4;
    const int b_row  = ((lane >> 4) << 3) + (lane & 7);
    const int b_byte = ((lane >> 3) & 1) << 4;

    #pragma unroll 1
    for (int it = 0; it < iters; ++it) {
        if (it + 1 < iters) { CP_WAIT(1); } else { CP_WAIT(0); }
        __syncthreads();

        if (it + 2 < iters) {
            load_stage(it + 2, (it + 2) % NSTAGE);
            CP_COMMIT();
        }

        const uint32_t stg = sb + (it % NSTAGE) * STAGE_BYTES;
        const uint32_t aARow = stg + (warp_m + a_row) * RSB + a_byte;
        const uint32_t aBRow = stg + (warp_n + b_row) * RSB + b_byte;

        #pragma unroll
        for (int kc = 0; kc < 2; kc++) {
            const uint32_t kb = kc * 32;
            uint32_t ah[4][4], al[4][4], bb[8][2];
            #pragma unroll
            for (int i = 0; i < 4; i++) {
                ldsm_x4(ah[i][0], ah[i][1], ah[i][2], ah[i][3],
                        aARow + OFF_AH + i * 16 * RSB + kb);
                ldsm_x4(al[i][0], al[i][1], al[i][2], al[i][3],
                        aARow + OFF_AL + i * 16 * RSB + kb);
            }
            #pragma unroll
            for (int jj = 0; jj < 4; jj++) {
                ldsm_x4(bb[2*jj][0], bb[2*jj][1], bb[2*jj+1][0], bb[2*jj+1][1],
                        aBRow + OFF_B + jj * 16 * RSB + kb);
            }
            #pragma unroll
            for (int i = 0; i < 4; i++)
                #pragma unroll
                for (int j = 0; j < 8; j++) {
                    mma16816(acc[i][j], ah[i][0], ah[i][1], ah[i][2], ah[i][3],
                             bb[j][0], bb[j][1]);
                    mma16816(acc[i][j], al[i][0], al[i][1], al[i][2], al[i][3],
                             bb[j][0], bb[j][1]);
                }
        }
        // no trailing barrier needed with 3-stage rotation
    }

    const int er = lane >> 2;
    const int ec = (lane & 3) * 2;
    if (Chi && Clo) {
        #pragma unroll
        for (int i = 0; i < 4; i++)
            #pragma unroll
            for (int j = 0; j < 8; j++) {
                int row = m0 + warp_m + i * 16 + er;
                int col = n0 + warp_n + j * 8 + ec;
                uint32_t h0, l0, h1, l1;
                pack_split_h(acc[i][j][0], acc[i][j][1], h0, l0);
                pack_split_h(acc[i][j][2], acc[i][j][3], h1, l1);
                *(uint32_t*)(Chi + (size_t)row * N + col)       = h0;
                *(uint32_t*)(Clo + (size_t)row * N + col)       = l0;
                *(uint32_t*)(Chi + (size_t)(row + 8) * N + col) = h1;
                *(uint32_t*)(Clo + (size_t)(row + 8) * N + col) = l1;
            }
    } else if (Chi) {
        #pragma unroll
        for (int i = 0; i < 4; i++)
            #pragma unroll
            for (int j = 0; j < 8; j++) {
                int row = m0 + warp_m + i * 16 + er;
                int col = n0 + warp_n + j * 8 + ec;
                *(uint32_t*)(Chi + (size_t)row * N + col) =
                    pack_h2(acc[i][j][0], acc[i][j][1]);
                *(uint32_t*)(Chi + (size_t)(row + 8) * N + col) =
                    pack_h2(acc[i][j][2], acc[i][j][3]);
            }
    } else {
        #pragma unroll
        for (int i = 0; i < 4; i++)
            #pragma unroll
            for (int j = 0; j < 8; j++) {
                int row = m0 + warp_m + i * 16 + er;
                int col = n0 + warp_n + j * 8 + ec;
                float* p0 = C + (size_t)row * N + col;
                float* p1 = C + (size_t)(row + 8) * N + col;
                p0[0] = acc[i][j][0]; p0[1] = acc[i][j][1];
                p1[0] = acc[i][j][2]; p1[1] = acc[i][j][3];
            }
    }
}

// ---------------------------------------------------------------------------
// Tensor-core segment attention (fp16x2 HMMA, softmax in fragments).
// One block per (b, h, seg): 128 threads = 4 warps, 32 q-rows per warp.
// smem: swizzled fp16 tiles Qh/Ql[128x64], K[64x64], V[64x64] = 48KB.
// ---------------------------------------------------------------------------
#define ASM_QH 0
#define ASM_QL 16384
#define ASM_K  32768
#define ASM_V  40960
#define ATTN_SMEM 49152
// swizzled address within a tile: row stride 128B, 16B chunks XOR'd by row&7
#define SWIZ(base, row, ch) ((base) + (row) * 128 + ((((ch) ^ ((row) & 7))) << 4))

__global__ __launch_bounds__(128) void attn_kernel() {
    extern __shared__ char asmem[];
    const uint32_t sb = smem_to_u32(asmem);

    const int bid = blockIdx.x;
    const int n = bid % NSEG;
    const int h = (bid / NSEG) % NH;
    const int b = bid / (NSEG * NH);
    const int tid = threadIdx.x;
    const int lane = tid & 31;
    const int wid = tid >> 5;
    const int warp_m = wid * 32;

    // ---- load Q (hi/lo): 2048 16B chunks ----
    #pragma unroll
    for (int i = 0; i < 16; i++) {
        int c = i * 128 + tid;
        int mat = c >> 10;              // 0=hi 1=lo
        int rc  = c & 1023;
        int row = rc >> 3, ch = rc & 7;
        int sq = hmap(n * SEG + row);
        const __half* g = (mat ? g_qlo : g_qhi) +
            ((size_t)(b * S_LEN + sq)) * DM + h * DH + ch * 8;
        cp_async16(SWIZ(sb + (mat ? ASM_QL : ASM_QH), row, ch), g);
    }
    // ---- load K and V: 1024 16B chunks ----
    #pragma unroll
    for (int i = 0; i < 8; i++) {
        int c = i * 128 + tid;
        int kv  = c >> 9;               // 0=K 1=V
        int rc  = c & 511;
        int row = rc >> 3, ch = rc & 7;
        size_t go = ((size_t)b * 4096 + n * 64 + row) * (2 * DM)
                  + (size_t)kv * DM + h * DH + ch * 8;
        cp_async16(SWIZ(sb + (kv ? ASM_V : ASM_K), row, ch), g_kv + go);
    }
    CP_COMMIT();
    CP_WAIT(0);
    __syncthreads();

    // ---- scores: S = Q @ K^T ----
    float acc_s[2][8][4];
    #pragma unroll
    for (int i = 0; i < 2; i++)
        #pragma unroll
        for (int j = 0; j < 8; j++)
            #pragma unroll
            for (int q = 0; q < 4; q++) acc_s[i][j][q] = 0.0f;

    const int a_r  = lane & 15;
    const int a_c  = lane >> 4;
    const int b_r  = ((lane >> 4) << 3) + (lane & 7);
    const int b_c  = (lane >> 3) & 1;

    #pragma unroll
    for (int t = 0; t < 4; t++) {
        uint32_t qh[2][4], ql[2][4], kk[8][2];
        #pragma unroll
        for (int i = 0; i < 2; i++) {
            int row = warp_m + i * 16 + a_r;
            int ch = 2 * t + a_c;
            ldsm_x4(qh[i][0], qh[i][1], qh[i][2], qh[i][3],
                    SWIZ(sb + ASM_QH, row, ch));
            ldsm_x4(ql[i][0], ql[i][1], ql[i][2], ql[i][3],
                    SWIZ(sb + ASM_QL, row, ch));
        }
        #pragma unroll
        for (int jj = 0; jj < 4; jj++) {
            int row = jj * 16 + b_r;
            int ch = 2 * t + b_c;
            ldsm_x4(kk[2*jj][0], kk[2*jj][1], kk[2*jj+1][0], kk[2*jj+1][1],
                    SWIZ(sb + ASM_K, row, ch));
        }
        #pragma unroll
        for (int i = 0; i < 2; i++)
            #pragma unroll
            for (int j = 0; j < 8; j++) {
                mma16816(acc_s[i][j], qh[i][0], qh[i][1], qh[i][2], qh[i][3],
                         kk[j][0], kk[j][1]);
                mma16816(acc_s[i][j], ql[i][0], ql[i][1], ql[i][2], ql[i][3],
                         kk[j][0], kk[j][1]);
            }
    }

    // ---- softmax over 64 cols, per fragment row (quad shfl reduce) ----
    #pragma unroll
    for (int i = 0; i < 2; i++) {
        #pragma unroll
        for (int half = 0; half < 2; half++) {
            float mx = -1e30f;
            #pragma unroll
            for (int j = 0; j < 8; j++) {
                mx = fmaxf(mx, acc_s[i][j][half*2]);
                mx = fmaxf(mx, acc_s[i][j][half*2+1]);
            }
            mx = fmaxf(mx, __shfl_xor_sync(0xffffffffu, mx, 1));
            mx = fmaxf(mx, __shfl_xor_sync(0xffffffffu, mx, 2));
            float sum = 0.0f;
            #pragma unroll
            for (int j = 0; j < 8; j++) {
                float p0 = expf((acc_s[i][j][half*2]   - mx) * 0.125f);
                float p1 = expf((acc_s[i][j][half*2+1] - mx) * 0.125f);
                acc_s[i][j][half*2]   = p0;
                acc_s[i][j][half*2+1] = p1;
                sum += p0 + p1;
            }
            sum += __shfl_xor_sync(0xffffffffu, sum, 1);
            sum += __shfl_xor_sync(0xffffffffu, sum, 2);
            float inv = 1.0f / sum;
            #pragma unroll
            for (int j = 0; j < 8; j++) {
                acc_s[i][j][half*2]   *= inv;
                acc_s[i][j][half*2+1] *= inv;
            }
        }
    }

    // ---- O = P @ V  (P split fp16 in frags, V^T frags via ldmatrix.trans) ----
    float acc_o[2][8][4];
    #pragma unroll
    for (int i = 0; i < 2; i++)
        #pragma unroll
        for (int j = 0; j < 8; j++)
            #pragma unroll
            for (int q = 0; q < 4; q++) acc_o[i][j][q] = 0.0f;

    #pragma unroll
    for (int t = 0; t < 4; t++) {
        uint32_t ph[2][4], pl[2][4];
        #pragma unroll
        for (int i = 0; i < 2; i++) {
            pack_split_h(acc_s[i][2*t][0],   acc_s[i][2*t][1],   ph[i][0], pl[i][0]);
            pack_split_h(acc_s[i][2*t][2],   acc_s[i][2*t][3],   ph[i][1], pl[i][1]);
            pack_split_h(acc_s[i][2*t+1][0], acc_s[i][2*t+1][1], ph[i][2], pl[i][2]);
            pack_split_h(acc_s[i][2*t+1][2], acc_s[i][2*t+1][3], ph[i][3], pl[i][3]);
        }
        uint32_t vv[8][2];
        #pragma unroll
        for (int jj = 0; jj < 4; jj++) {
            int row = t * 16 + (lane & 15);
            int ch = jj * 2 + (lane >> 4);
            ldsm_x4_t(vv[2*jj][0], vv[2*jj][1], vv[2*jj+1][0], vv[2*jj+1][1],
                      SWIZ(sb + ASM_V, row, ch));
        }
        #pragma unroll
        for (int i = 0; i < 2; i++)
            #pragma unroll
            for (int nd = 0; nd < 8; nd++) {
                mma16816(acc_o[i][nd], ph[i][0], ph[i][1], ph[i][2], ph[i][3],
                         vv[nd][0], vv[nd][1]);
                mma16816(acc_o[i][nd], pl[i][0], pl[i][1], pl[i][2], pl[i][3],
                         vv[nd][0], vv[nd][1]);
            }
    }

    // ---- epilogue: scatter rows back by map, write fp16 hi/lo split ----
    const int er = lane >> 2;
    const int ec = (lane & 3) * 2;
    #pragma unroll
    for (int i = 0; i < 2; i++) {
        #pragma unroll
        for (int half = 0; half < 2; half++) {
            int rowl = warp_m + i * 16 + er + half * 8;
            int sq = hmap(n * SEG + rowl);
            size_t gr = ((size_t)(b * S_LEN + sq)) * DM + h * DH;
            #pragma unroll
            for (int nd = 0; nd < 8; nd++) {
                uint32_t hi, lo;
                pack_split_h(acc_o[i][nd][half*2], acc_o[i][nd][half*2+1], hi, lo);
                *(uint32_t*)(g_ahi + gr + nd * 8 + ec) = hi;
                *(uint32_t*)(g_alo + gr + nd * 8 + ec) = lo;
            }
        }
    }
}

// ---------------------------------------------------------------------------
// Launch
// ---------------------------------------------------------------------------
extern "C" void kernel_launch(void* const* d_in, const int* in_sizes, int n_in,
                              void* d_out, int out_size)
{
    const float* x    = (const float*)d_in[0];   // [2,8192,1024]
    const float* wqkv = (const float*)d_in[1];   // [1024,3072]
    const float* wout = (const float*)d_in[2];   // [1024,1024]
    float*       out  = (float*)d_out;           // [2,8192,1024]

    __half *xhi, *xlo, *qhi, *qlo, *kv, *ahi, *alo, *wq, *wo;
    int *rowkv_p;
    cudaGetSymbolAddress((void**)&xhi, g_xhi);
    cudaGetSymbolAddress((void**)&xlo, g_xlo);
    cudaGetSymbolAddress((void**)&qhi, g_qhi);
    cudaGetSymbolAddress((void**)&qlo, g_qlo);
    cudaGetSymbolAddress((void**)&kv,  g_kv);
    cudaGetSymbolAddress((void**)&ahi, g_ahi);
    cudaGetSymbolAddress((void**)&alo, g_alo);
    cudaGetSymbolAddress((void**)&wq,  g_wq);
    cudaGetSymbolAddress((void**)&wo,  g_wo);
    cudaGetSymbolAddress((void**)&rowkv_p, g_rowkv);

    static bool attr_set = false;
    if (!attr_set) {
        cudaFuncSetAttribute(gemm_fp16x2,
            cudaFuncAttributeMaxDynamicSharedMemorySize, GEMM_SMEM);
        cudaFuncSetAttribute(attn_kernel,
            cudaFuncAttributeMaxDynamicSharedMemorySize, ATTN_SMEM);
        attr_set = true;
    }

    // 1. prep
    rowkv_kernel<<<(KVROWS + 255) / 256, 256>>>();
    split_kernel<<<(MROWS * DM / 4 + 255) / 256, 256>>>(x, xhi, xlo, MROWS * DM / 4);
    {
        dim3 blk(32, 8);
        transpose_h_kernel<<<dim3(3 * DM / 32, DM / 32), blk>>>(wqkv, wq, DM, 3 * DM);
        transpose_h_kernel<<<dim3(DM / 32, DM / 32), blk>>>(wout, wo, DM, DM);
    }

    // 2a. Q projection -> fp16 split
    gemm_fp16x2<<<dim3(DM / GBN, MROWS / GBM), 256, GEMM_SMEM>>>(
        MROWS, DM, DM, xhi, xlo, wq, nullptr, nullptr, qhi, qlo);

    // 2b. K/V projection (gathered dilated rows) -> fp16 single
    gemm_fp16x2<<<dim3(2 * DM / GBN, KVROWS / GBM), 256, GEMM_SMEM>>>(
        KVROWS, 2 * DM, DM, xhi, xlo, wq + (size_t)DM * DM, rowkv_p,
        nullptr, kv, nullptr);

    // 3. tensor-core segment attention -> fp16 split
    attn_kernel<<<B_SZ * NH * NSEG, 128, ATTN_SMEM>>>();

    // 4. output projection -> fp32 final
    gemm_fp16x2<<<dim3(DM / GBN, MROWS / GBM), 256, GEMM_SMEM>>>(
        MROWS, DM, DM, ahi, alo, wo, nullptr, out, nullptr, nullptr);
}

// round 7
// speedup vs baseline: 5.9656x; 1.4612x over previous
#include <cuda_runtime.h>
#include <cuda_fp16.h>
#include <cstdint>
#include <math.h>

// Problem constants (fixed by the dataset)
#define S_LEN  8192
#define B_SZ   2
#define DM     1024
#define NH     16
#define DH     64
#define SEG    128
#define NSEG   (S_LEN / SEG)     // 64
#define GRID_G 91                // ceil(sqrt(8192))

#define MROWS  (B_SZ * S_LEN)      // 16384
#define KVROWS (B_SZ * S_LEN / 2)  // 8192 compacted K/V rows

// ---------------------------------------------------------------------------
// Scratch (allocation-free rule: __device__ globals)
// ---------------------------------------------------------------------------
__device__ __half  g_x   [MROWS * DM];          // x fp16 (A-side GEMM1)
__device__ __half  g_qhi [MROWS * DM];          // Q fp16 hi (exact split of fp32 Q)
__device__ __half  g_qlo [MROWS * DM];
__device__ __half  g_kv  [KVROWS * 2 * DM];     // compact [K|V] fp16
__device__ __half  g_a   [MROWS * DM];          // attn-out fp16 (A-side out-proj)
__device__ __half  g_wq  [3 * DM * DM];         // W_qkv^T fp16 [3072,1024]
__device__ __half  g_wo  [DM * DM];             // W_out^T fp16 [1024,1024]
__device__ int     g_rowkv[KVROWS];             // gathered A rows for K/V GEMM

// ---------------------------------------------------------------------------
// PTX helpers (compute_103-safe subset: ldmatrix / mma.sync / cp.async)
// ---------------------------------------------------------------------------
__device__ __forceinline__ uint32_t smem_to_u32(const void* p) {
    uint32_t a;
    asm("{ .reg .u64 t; cvta.to.shared.u64 t, %1; cvt.u32.u64 %0, t; }"
        : "=r"(a) : "l"(p));
    return a;
}
__device__ __forceinline__ void cp_async16(uint32_t saddr, const void* gptr) {
    asm volatile("cp.async.cg.shared.global [%0], [%1], 16;"
                 :: "r"(saddr), "l"(gptr));
}
#define CP_COMMIT() asm volatile("cp.async.commit_group;")
#define CP_WAIT(n)  asm volatile("cp.async.wait_group %0;" :: "n"(n))

__device__ __forceinline__ void ldsm_x4(uint32_t& r0, uint32_t& r1,
                                        uint32_t& r2, uint32_t& r3,
                                        uint32_t addr) {
    asm volatile("ldmatrix.sync.aligned.m8n8.x4.shared.b16 {%0,%1,%2,%3}, [%4];"
                 : "=r"(r0), "=r"(r1), "=r"(r2), "=r"(r3) : "r"(addr));
}
__device__ __forceinline__ void ldsm_x4_t(uint32_t& r0, uint32_t& r1,
                                          uint32_t& r2, uint32_t& r3,
                                          uint32_t addr) {
    asm volatile("ldmatrix.sync.aligned.m8n8.x4.trans.shared.b16 {%0,%1,%2,%3}, [%4];"
                 : "=r"(r0), "=r"(r1), "=r"(r2), "=r"(r3) : "r"(addr));
}
__device__ __forceinline__ void mma16816(float* c,
                                         uint32_t a0, uint32_t a1,
                                         uint32_t a2, uint32_t a3,
                                         uint32_t b0, uint32_t b1) {
    asm volatile(
        "mma.sync.aligned.m16n8k16.row.col.f32.f16.f16.f32 "
        "{%0,%1,%2,%3}, {%4,%5,%6,%7}, {%8,%9}, {%0,%1,%2,%3};"
        : "+f"(c[0]), "+f"(c[1]), "+f"(c[2]), "+f"(c[3])
        : "r"(a0), "r"(a1), "r"(a2), "r"(a3), "r"(b0), "r"(b1));
}

__device__ __forceinline__ uint32_t pack_h2(float a, float b) {
    __half2 t = __halves2half2(__float2half_rn(a), __float2half_rn(b));
    return *(uint32_t*)&t;
}
// hi/lo split pack: hi = fp16(v), lo = fp16(v - hi)
__device__ __forceinline__ void pack_split_h(float a, float b,
                                             uint32_t& hi, uint32_t& lo) {
    __half ha = __float2half_rn(a);
    __half hb = __float2half_rn(b);
    __half2 th = __halves2half2(ha, hb);
    __half2 tl = __halves2half2(__float2half_rn(a - __half2float(ha)),
                                __float2half_rn(b - __half2float(hb)));
    hi = *(uint32_t*)&th;
    lo = *(uint32_t*)&tl;
}

// ---------------------------------------------------------------------------
// Closed-form boustrophedon map
// ---------------------------------------------------------------------------
__device__ __forceinline__ int hmap(int lp) {
    int r = lp / GRID_G;
    int c = lp % GRID_G;
    int vr = min(GRID_G, S_LEN - r * GRID_G);
    return ((r & 1) == 0) ? (r * GRID_G + c) : (r * GRID_G + vr - 1 - c);
}

// Row list for the gathered K/V GEMM
__global__ void rowkv_kernel() {
    int i = blockIdx.x * 256 + threadIdx.x;
    if (i >= KVROWS) return;
    int b = i >> 12;
    int r = i & 4095;
    int n = r >> 6, j = r & 63;
    g_rowkv[i] = b * S_LEN + hmap(n * SEG + 2 * j);
}

// ---------------------------------------------------------------------------
// fp32 -> fp16 convert
// ---------------------------------------------------------------------------
__global__ __launch_bounds__(256) void cvt_kernel(
    const float* __restrict__ src, __half* __restrict__ dst, int n4)
{
    int i = blockIdx.x * 256 + threadIdx.x;
    if (i >= n4) return;
    float4 v = ((const float4*)src)[i];
    ((uint32_t*)dst)[2 * i]     = pack_h2(v.x, v.y);
    ((uint32_t*)dst)[2 * i + 1] = pack_h2(v.z, v.w);
}

// ---------------------------------------------------------------------------
// W [K,N] fp32 -> W^T [N,K] fp16 (tiled transpose)
// ---------------------------------------------------------------------------
__global__ __launch_bounds__(256) void transpose_h_kernel(
    const float* __restrict__ W, __half* __restrict__ T, int K, int N)
{
    __shared__ float t[32][33];
    int n0 = blockIdx.x * 32, k0 = blockIdx.y * 32;
    int tx = threadIdx.x, ty = threadIdx.y;    // block (32, 8)
    #pragma unroll
    for (int i = 0; i < 4; i++)
        t[ty + 8 * i][tx] = W[(size_t)(k0 + ty + 8 * i) * N + n0 + tx];
    __syncthreads();
    #pragma unroll
    for (int i = 0; i < 4; i++) {
        size_t o = (size_t)(n0 + ty + 8 * i) * K + k0 + tx;
        T[o] = __float2half_rn(t[tx][ty + 8 * i]);
    }
}

// ---------------------------------------------------------------------------
// HMMA fp16 GEMM: C[M,N] = A[rows][K] @ B[N,K]^T, fp32 acc, 1 MMA/product.
// BM=128, BN=256, BK=32, 256 threads, 4-stage cp.async pipeline.
// Output modes: fp32 C, fp16 split (Chi+Clo), or fp16 single (Chi).
// ---------------------------------------------------------------------------
#define GBM 128
#define GBN 256
#define GBK 32
#define RSB 80                         // 32 fp16 + 8 pad = 80 bytes/row
#define OFF_A   0
#define OFF_B   (GBM * RSB)            // 10240
#define STAGE_BYTES ((GBM + GBN) * RSB)  // 30720
#define NSTAGE  4
#define GEMM_SMEM (NSTAGE * STAGE_BYTES) // 122880

__global__ __launch_bounds__(256, 1) void gemm_fp16(
    int M, int N, int K,
    const __half* __restrict__ A, const __half* __restrict__ B,
    const int* __restrict__ rowlist,
    float* __restrict__ C,
    __half* __restrict__ Chi, __half* __restrict__ Clo)
{
    extern __shared__ char smem[];
    __shared__ int srl[GBM];
    const uint32_t sb = smem_to_u32(smem);
    const int tid  = threadIdx.x;
    const int wid  = tid >> 5;
    const int lane = tid & 31;

    const int m0 = blockIdx.y * GBM;
    const int n0 = blockIdx.x * GBN;
    const int iters = K >> 5;

    if (tid < GBM) srl[tid] = rowlist ? rowlist[m0 + tid] : (m0 + tid);
    __syncthreads();

    const int warp_m = (wid & 1) * 64;
    const int warp_n = (wid >> 1) * 64;

    float acc[4][8][4];
    #pragma unroll
    for (int i = 0; i < 4; i++)
        #pragma unroll
        for (int j = 0; j < 8; j++)
            #pragma unroll
            for (int q = 0; q < 4; q++) acc[i][j][q] = 0.0f;

    // 1536 16B chunks per stage, 6 per thread
    auto load_stage = [&](int it, int stage) {
        const uint32_t stg = sb + stage * STAGE_BYTES;
        const int k0 = it * GBK;
        #pragma unroll
        for (int i = 0; i < 6; i++) {
            int c = i * 256 + tid;
            const __half* g;
            uint32_t soff;
            if (c < 512) {             // A: 128 rows x 4 chunks
                int row = c >> 2, kc = c & 3;
                g = A + (size_t)srl[row] * K + k0 + kc * 8;
                soff = OFF_A + row * RSB + kc * 16;
            } else {                   // B: 256 rows x 4 chunks
                int c2 = c - 512;
                int row = c2 >> 2, kc = c2 & 3;
                g = B + (size_t)(n0 + row) * K + k0 + kc * 8;
                soff = OFF_B + row * RSB + kc * 16;
            }
            cp_async16(stg + soff, g);
        }
    };

    load_stage(0, 0); CP_COMMIT();
    load_stage(1, 1); CP_COMMIT();
    load_stage(2, 2); CP_COMMIT();

    const int a_row  = lane & 15;
    const int a_byte = (lane >> 4) << 4;
    const int b_row  = ((lane >> 4) << 3) + (lane & 7);
    const int b_byte = ((lane >> 3) & 1) << 4;

    #pragma unroll 1
    for (int it = 0; it < iters; ++it) {
        if (it + 1 >= iters)      { CP_WAIT(0); }
        else if (it + 2 >= iters) { CP_WAIT(1); }
        else                      { CP_WAIT(2); }
        __syncthreads();

        if (it + 3 < iters) {
            load_stage(it + 3, (it + 3) & (NSTAGE - 1));
            CP_COMMIT();
        }

        const uint32_t stg = sb + (it & (NSTAGE - 1)) * STAGE_BYTES;
        const uint32_t aARow = stg + (warp_m + a_row) * RSB + a_byte;
        const uint32_t aBRow = stg + (warp_n + b_row) * RSB + b_byte;

        #pragma unroll
        for (int kc = 0; kc < 2; kc++) {
            const uint32_t kb = kc * 32;
            uint32_t aa[4][4], bb[8][2];
            #pragma unroll
            for (int i = 0; i < 4; i++)
                ldsm_x4(aa[i][0], aa[i][1], aa[i][2], aa[i][3],
                        aARow + OFF_A + i * 16 * RSB + kb);
            #pragma unroll
            for (int jj = 0; jj < 4; jj++)
                ldsm_x4(bb[2*jj][0], bb[2*jj][1], bb[2*jj+1][0], bb[2*jj+1][1],
                        aBRow + OFF_B + jj * 16 * RSB + kb);
            #pragma unroll
            for (int i = 0; i < 4; i++)
                #pragma unroll
                for (int j = 0; j < 8; j++)
                    mma16816(acc[i][j], aa[i][0], aa[i][1], aa[i][2], aa[i][3],
                             bb[j][0], bb[j][1]);
        }
    }

    const int er = lane >> 2;
    const int ec = (lane & 3) * 2;
    if (Chi && Clo) {
        #pragma unroll
        for (int i = 0; i < 4; i++)
            #pragma unroll
            for (int j = 0; j < 8; j++) {
                int row = m0 + warp_m + i * 16 + er;
                int col = n0 + warp_n + j * 8 + ec;
                uint32_t h0, l0, h1, l1;
                pack_split_h(acc[i][j][0], acc[i][j][1], h0, l0);
                pack_split_h(acc[i][j][2], acc[i][j][3], h1, l1);
                *(uint32_t*)(Chi + (size_t)row * N + col)       = h0;
                *(uint32_t*)(Clo + (size_t)row * N + col)       = l0;
                *(uint32_t*)(Chi + (size_t)(row + 8) * N + col) = h1;
                *(uint32_t*)(Clo + (size_t)(row + 8) * N + col) = l1;
            }
    } else if (Chi) {
        #pragma unroll
        for (int i = 0; i < 4; i++)
            #pragma unroll
            for (int j = 0; j < 8; j++) {
                int row = m0 + warp_m + i * 16 + er;
                int col = n0 + warp_n + j * 8 + ec;
                *(uint32_t*)(Chi + (size_t)row * N + col) =
                    pack_h2(acc[i][j][0], acc[i][j][1]);
                *(uint32_t*)(Chi + (size_t)(row + 8) * N + col) =
                    pack_h2(acc[i][j][2], acc[i][j][3]);
            }
    } else {
        #pragma unroll
        for (int i = 0; i < 4; i++)
            #pragma unroll
            for (int j = 0; j < 8; j++) {
                int row = m0 + warp_m + i * 16 + er;
                int col = n0 + warp_n + j * 8 + ec;
                float* p0 = C + (size_t)row * N + col;
                float* p1 = C + (size_t)(row + 8) * N + col;
                p0[0] = acc[i][j][0]; p0[1] = acc[i][j][1];
                p1[0] = acc[i][j][2]; p1[1] = acc[i][j][3];
            }
    }
}

// ---------------------------------------------------------------------------
// Tensor-core segment attention (fp16 HMMA, softmax in fragments).
// Q exact (hi/lo from GEMM1 epilogue), K/V single fp16, P exact split.
// One block per (b, h, seg): 128 threads = 4 warps, 32 q-rows per warp.
// smem: swizzled fp16 tiles Qh/Ql[128x64], K[64x64], V[64x64] = 48KB.
// ---------------------------------------------------------------------------
#define ASM_QH 0
#define ASM_QL 16384
#define ASM_K  32768
#define ASM_V  40960
#define ATTN_SMEM 49152
// swizzled address within a tile: row stride 128B, 16B chunks XOR'd by row&7
#define SWIZ(base, row, ch) ((base) + (row) * 128 + ((((ch) ^ ((row) & 7))) << 4))

__global__ __launch_bounds__(128) void attn_kernel() {
    extern __shared__ char asmem[];
    const uint32_t sb = smem_to_u32(asmem);

    const int bid = blockIdx.x;
    const int n = bid % NSEG;
    const int h = (bid / NSEG) % NH;
    const int b = bid / (NSEG * NH);
    const int tid = threadIdx.x;
    const int lane = tid & 31;
    const int wid = tid >> 5;
    const int warp_m = wid * 32;

    // ---- load Q (hi/lo): 2048 16B chunks ----
    #pragma unroll
    for (int i = 0; i < 16; i++) {
        int c = i * 128 + tid;
        int mat = c >> 10;              // 0=hi 1=lo
        int rc  = c & 1023;
        int row = rc >> 3, ch = rc & 7;
        int sq = hmap(n * SEG + row);
        const __half* g = (mat ? g_qlo : g_qhi) +
            ((size_t)(b * S_LEN + sq)) * DM + h * DH + ch * 8;
        cp_async16(SWIZ(sb + (mat ? ASM_QL : ASM_QH), row, ch), g);
    }
    // ---- load K and V: 1024 16B chunks ----
    #pragma unroll
    for (int i = 0; i < 8; i++) {
        int c = i * 128 + tid;
        int kv  = c >> 9;               // 0=K 1=V
        int rc  = c & 511;
        int row = rc >> 3, ch = rc & 7;
        size_t go = ((size_t)b * 4096 + n * 64 + row) * (2 * DM)
                  + (size_t)kv * DM + h * DH + ch * 8;
        cp_async16(SWIZ(sb + (kv ? ASM_V : ASM_K), row, ch), g_kv + go);
    }
    CP_COMMIT();
    CP_WAIT(0);
    __syncthreads();

    // ---- scores: S = Q @ K^T ----
    float acc_s[2][8][4];
    #pragma unroll
    for (int i = 0; i < 2; i++)
        #pragma unroll
        for (int j = 0; j < 8; j++)
            #pragma unroll
            for (int q = 0; q < 4; q++) acc_s[i][j][q] = 0.0f;

    const int a_r  = lane & 15;
    const int a_c  = lane >> 4;
    const int b_r  = ((lane >> 4) << 3) + (lane & 7);
    const int b_c  = (lane >> 3) & 1;

    #pragma unroll
    for (int t = 0; t < 4; t++) {
        uint32_t qh[2][4], ql[2][4], kk[8][2];
        #pragma unroll
        for (int i = 0; i < 2; i++) {
            int row = warp_m + i * 16 + a_r;
            int ch = 2 * t + a_c;
            ldsm_x4(qh[i][0], qh[i][1], qh[i][2], qh[i][3],
                    SWIZ(sb + ASM_QH, row, ch));
            ldsm_x4(ql[i][0], ql[i][1], ql[i][2], ql[i][3],
                    SWIZ(sb + ASM_QL, row, ch));
        }
        #pragma unroll
        for (int jj = 0; jj < 4; jj++) {
            int row = jj * 16 + b_r;
            int ch = 2 * t + b_c;
            ldsm_x4(kk[2*jj][0], kk[2*jj][1], kk[2*jj+1][0], kk[2*jj+1][1],
                    SWIZ(sb + ASM_K, row, ch));
        }
        #pragma unroll
        for (int i = 0; i < 2; i++)
            #pragma unroll
            for (int j = 0; j < 8; j++) {
                mma16816(acc_s[i][j], qh[i][0], qh[i][1], qh[i][2], qh[i][3],
                         kk[j][0], kk[j][1]);
                mma16816(acc_s[i][j], ql[i][0], ql[i][1], ql[i][2], ql[i][3],
                         kk[j][0], kk[j][1]);
            }
    }

    // ---- softmax over 64 cols, per fragment row (quad shfl reduce) ----
    #pragma unroll
    for (int i = 0; i < 2; i++) {
        #pragma unroll
        for (int half = 0; half < 2; half++) {
            float mx = -1e30f;
            #pragma unroll
            for (int j = 0; j < 8; j++) {
                mx = fmaxf(mx, acc_s[i][j][half*2]);
                mx = fmaxf(mx, acc_s[i][j][half*2+1]);
            }
            mx = fmaxf(mx, __shfl_xor_sync(0xffffffffu, mx, 1));
            mx = fmaxf(mx, __shfl_xor_sync(0xffffffffu, mx, 2));
            float sum = 0.0f;
            #pragma unroll
            for (int j = 0; j < 8; j++) {
                float p0 = expf((acc_s[i][j][half*2]   - mx) * 0.125f);
                float p1 = expf((acc_s[i][j][half*2+1] - mx) * 0.125f);
                acc_s[i][j][half*2]   = p0;
                acc_s[i][j][half*2+1] = p1;
                sum += p0 + p1;
            }
            sum += __shfl_xor_sync(0xffffffffu, sum, 1);
            sum += __shfl_xor_sync(0xffffffffu, sum, 2);
            float inv = 1.0f / sum;
            #pragma unroll
            for (int j = 0; j < 8; j++) {
                acc_s[i][j][half*2]   *= inv;
                acc_s[i][j][half*2+1] *= inv;
            }
        }
    }

    // ---- O = P @ V  (P split fp16 in frags, V^T frags via ldmatrix.trans) ----
    float acc_o[2][8][4];
    #pragma unroll
    for (int i = 0; i < 2; i++)
        #pragma unroll
        for (int j = 0; j < 8; j++)
            #pragma unroll
            for (int q = 0; q < 4; q++) acc_o[i][j][q] = 0.0f;

    #pragma unroll
    for (int t = 0; t < 4; t++) {
        uint32_t ph[2][4], pl[2][4];
        #pragma unroll
        for (int i = 0; i < 2; i++) {
            pack_split_h(acc_s[i][2*t][0],   acc_s[i][2*t][1],   ph[i][0], pl[i][0]);
            pack_split_h(acc_s[i][2*t][2],   acc_s[i][2*t][3],   ph[i][1], pl[i][1]);
            pack_split_h(acc_s[i][2*t+1][0], acc_s[i][2*t+1][1], ph[i][2], pl[i][2]);
            pack_split_h(acc_s[i][2*t+1][2], acc_s[i][2*t+1][3], ph[i][3], pl[i][3]);
        }
        uint32_t vv[8][2];
        #pragma unroll
        for (int jj = 0; jj < 4; jj++) {
            int row = t * 16 + (lane & 15);
            int ch = jj * 2 + (lane >> 4);
            ldsm_x4_t(vv[2*jj][0], vv[2*jj][1], vv[2*jj+1][0], vv[2*jj+1][1],
                      SWIZ(sb + ASM_V, row, ch));
        }
        #pragma unroll
        for (int i = 0; i < 2; i++)
            #pragma unroll
            for (int nd = 0; nd < 8; nd++) {
                mma16816(acc_o[i][nd], ph[i][0], ph[i][1], ph[i][2], ph[i][3],
                         vv[nd][0], vv[nd][1]);
                mma16816(acc_o[i][nd], pl[i][0], pl[i][1], pl[i][2], pl[i][3],
                         vv[nd][0], vv[nd][1]);
            }
    }

    // ---- epilogue: scatter rows back by map, write single fp16 ----
    const int er = lane >> 2;
    const int ec = (lane & 3) * 2;
    #pragma unroll
    for (int i = 0; i < 2; i++) {
        #pragma unroll
        for (int half = 0; half < 2; half++) {
            int rowl = warp_m + i * 16 + er + half * 8;
            int sq = hmap(n * SEG + rowl);
            size_t gr = ((size_t)(b * S_LEN + sq)) * DM + h * DH;
            #pragma unroll
            for (int nd = 0; nd < 8; nd++) {
                *(uint32_t*)(g_a + gr + nd * 8 + ec) =
                    pack_h2(acc_o[i][nd][half*2], acc_o[i][nd][half*2+1]);
            }
        }
    }
}

// ---------------------------------------------------------------------------
// Launch
// ---------------------------------------------------------------------------
extern "C" void kernel_launch(void* const* d_in, const int* in_sizes, int n_in,
                              void* d_out, int out_size)
{
    const float* x    = (const float*)d_in[0];   // [2,8192,1024]
    const float* wqkv = (const float*)d_in[1];   // [1024,3072]
    const float* wout = (const float*)d_in[2];   // [1024,1024]
    float*       out  = (float*)d_out;           // [2,8192,1024]

    __half *xp, *qhi, *qlo, *kv, *ap, *wq, *wo;
    int *rowkv_p;
    cudaGetSymbolAddress((void**)&xp,  g_x);
    cudaGetSymbolAddress((void**)&qhi, g_qhi);
    cudaGetSymbolAddress((void**)&qlo, g_qlo);
    cudaGetSymbolAddress((void**)&kv,  g_kv);
    cudaGetSymbolAddress((void**)&ap,  g_a);
    cudaGetSymbolAddress((void**)&wq,  g_wq);
    cudaGetSymbolAddress((void**)&wo,  g_wo);
    cudaGetSymbolAddress((void**)&rowkv_p, g_rowkv);

    static bool attr_set = false;
    if (!attr_set) {
        cudaFuncSetAttribute(gemm_fp16,
            cudaFuncAttributeMaxDynamicSharedMemorySize, GEMM_SMEM);
        cudaFuncSetAttribute(attn_kernel,
            cudaFuncAttributeMaxDynamicSharedMemorySize, ATTN_SMEM);
        attr_set = true;
    }

    // 1. prep
    rowkv_kernel<<<(KVROWS + 255) / 256, 256>>>();
    cvt_kernel<<<(MROWS * DM / 4 + 255) / 256, 256>>>(x, xp, MROWS * DM / 4);
    {
        dim3 blk(32, 8);
        transpose_h_kernel<<<dim3(3 * DM / 32, DM / 32), blk>>>(wqkv, wq, DM, 3 * DM);
        transpose_h_kernel<<<dim3(DM / 32, DM / 32), blk>>>(wout, wo, DM, DM);
    }

    // 2a. Q projection (single x single) -> exact fp16 split of fp32 result
    gemm_fp16<<<dim3(DM / GBN, MROWS / GBM), 256, GEMM_SMEM>>>(
        MROWS, DM, DM, xp, wq, nullptr, nullptr, qhi, qlo);

    // 2b. K/V projection (gathered dilated rows) -> fp16 single
    gemm_fp16<<<dim3(2 * DM / GBN, KVROWS / GBM), 256, GEMM_SMEM>>>(
        KVROWS, 2 * DM, DM, xp, wq + (size_t)DM * DM, rowkv_p,
        nullptr, kv, nullptr);

    // 3. tensor-core segment attention -> fp16 single
    attn_kernel<<<B_SZ * NH * NSEG, 128, ATTN_SMEM>>>();

    // 4. output projection -> fp32 final
    gemm_fp16<<<dim3(DM / GBN, MROWS / GBM), 256, GEMM_SMEM>>>(
        MROWS, DM, DM, ap, wo, nullptr, out, nullptr, nullptr);
}

// round 8
// speedup vs baseline: 6.6052x; 1.1072x over previous
#include <cuda_runtime.h>
#include <cuda_fp16.h>
#include <cstdint>
#include <math.h>

// Problem constants (fixed by the dataset)
#define S_LEN  8192
#define B_SZ   2
#define DM     1024
#define NH     16
#define DH     64
#define SEG    128
#define NSEG   (S_LEN / SEG)     // 64
#define GRID_G 91                // ceil(sqrt(8192))

#define MROWS  (B_SZ * S_LEN)      // 16384
#define KVROWS (B_SZ * S_LEN / 2)  // 8192 compacted K/V rows

// ---------------------------------------------------------------------------
// Scratch (allocation-free rule: __device__ globals)
// ---------------------------------------------------------------------------
__device__ __half  g_x   [MROWS * DM];          // x fp16
__device__ __half  g_q   [MROWS * DM];          // Q fp16 single
__device__ __half  g_kv  [KVROWS * 2 * DM];     // compact [K|V] fp16
__device__ __half  g_a   [MROWS * DM];          // attn-out fp16
__device__ __half  g_wq  [3 * DM * DM];         // W_qkv^T fp16 [3072,1024]
__device__ __half  g_wo  [DM * DM];             // W_out^T fp16 [1024,1024]
__device__ int     g_rowkv[KVROWS];             // gathered A rows for K/V GEMM

// ---------------------------------------------------------------------------
// PTX helpers (compute_103-safe subset: ldmatrix / mma.sync / cp.async)
// ---------------------------------------------------------------------------
__device__ __forceinline__ uint32_t smem_to_u32(const void* p) {
    uint32_t a;
    asm("{ .reg .u64 t; cvta.to.shared.u64 t, %1; cvt.u32.u64 %0, t; }"
        : "=r"(a) : "l"(p));
    return a;
}
__device__ __forceinline__ void cp_async16(uint32_t saddr, const void* gptr) {
    asm volatile("cp.async.cg.shared.global [%0], [%1], 16;"
                 :: "r"(saddr), "l"(gptr));
}
#define CP_COMMIT() asm volatile("cp.async.commit_group;")
#define CP_WAIT(n)  asm volatile("cp.async.wait_group %0;" :: "n"(n))

__device__ __forceinline__ void ldsm_x4(uint32_t& r0, uint32_t& r1,
                                        uint32_t& r2, uint32_t& r3,
                                        uint32_t addr) {
    asm volatile("ldmatrix.sync.aligned.m8n8.x4.shared.b16 {%0,%1,%2,%3}, [%4];"
                 : "=r"(r0), "=r"(r1), "=r"(r2), "=r"(r3) : "r"(addr));
}
__device__ __forceinline__ void ldsm_x4_t(uint32_t& r0, uint32_t& r1,
                                          uint32_t& r2, uint32_t& r3,
                                          uint32_t addr) {
    asm volatile("ldmatrix.sync.aligned.m8n8.x4.trans.shared.b16 {%0,%1,%2,%3}, [%4];"
                 : "=r"(r0), "=r"(r1), "=r"(r2), "=r"(r3) : "r"(addr));
}
__device__ __forceinline__ void mma16816(float* c,
                                         uint32_t a0, uint32_t a1,
                                         uint32_t a2, uint32_t a3,
                                         uint32_t b0, uint32_t b1) {
    asm volatile(
        "mma.sync.aligned.m16n8k16.row.col.f32.f16.f16.f32 "
        "{%0,%1,%2,%3}, {%4,%5,%6,%7}, {%8,%9}, {%0,%1,%2,%3};"
        : "+f"(c[0]), "+f"(c[1]), "+f"(c[2]), "+f"(c[3])
        : "r"(a0), "r"(a1), "r"(a2), "r"(a3), "r"(b0), "r"(b1));
}

__device__ __forceinline__ uint32_t pack_h2(float a, float b) {
    __half2 t = __halves2half2(__float2half_rn(a), __float2half_rn(b));
    return *(uint32_t*)&t;
}
// hi/lo split pack: hi = fp16(v), lo = fp16(v - hi)
__device__ __forceinline__ void pack_split_h(float a, float b,
                                             uint32_t& hi, uint32_t& lo) {
    __half ha = __float2half_rn(a);
    __half hb = __float2half_rn(b);
    __half2 th = __halves2half2(ha, hb);
    __half2 tl = __halves2half2(__float2half_rn(a - __half2float(ha)),
                                __float2half_rn(b - __half2float(hb)));
    hi = *(uint32_t*)&th;
    lo = *(uint32_t*)&tl;
}

// ---------------------------------------------------------------------------
// Closed-form boustrophedon map
// ---------------------------------------------------------------------------
__device__ __forceinline__ int hmap(int lp) {
    int r = lp / GRID_G;
    int c = lp % GRID_G;
    int vr = min(GRID_G, S_LEN - r * GRID_G);
    return ((r & 1) == 0) ? (r * GRID_G + c) : (r * GRID_G + vr - 1 - c);
}

// Row list for the gathered K/V GEMM
__global__ void rowkv_kernel() {
    int i = blockIdx.x * 256 + threadIdx.x;
    if (i >= KVROWS) return;
    int b = i >> 12;
    int r = i & 4095;
    int n = r >> 6, j = r & 63;
    g_rowkv[i] = b * S_LEN + hmap(n * SEG + 2 * j);
}

// ---------------------------------------------------------------------------
// fp32 -> fp16 convert
// ---------------------------------------------------------------------------
__global__ __launch_bounds__(256) void cvt_kernel(
    const float* __restrict__ src, __half* __restrict__ dst, int n4)
{
    int i = blockIdx.x * 256 + threadIdx.x;
    if (i >= n4) return;
    float4 v = ((const float4*)src)[i];
    ((uint32_t*)dst)[2 * i]     = pack_h2(v.x, v.y);
    ((uint32_t*)dst)[2 * i + 1] = pack_h2(v.z, v.w);
}

// ---------------------------------------------------------------------------
// W [K,N] fp32 -> W^T [N,K] fp16 (tiled transpose)
// ---------------------------------------------------------------------------
__global__ __launch_bounds__(256) void transpose_h_kernel(
    const float* __restrict__ W, __half* __restrict__ T, int K, int N)
{
    __shared__ float t[32][33];
    int n0 = blockIdx.x * 32, k0 = blockIdx.y * 32;
    int tx = threadIdx.x, ty = threadIdx.y;    // block (32, 8)
    #pragma unroll
    for (int i = 0; i < 4; i++)
        t[ty + 8 * i][tx] = W[(size_t)(k0 + ty + 8 * i) * N + n0 + tx];
    __syncthreads();
    #pragma unroll
    for (int i = 0; i < 4; i++) {
        size_t o = (size_t)(n0 + ty + 8 * i) * K + k0 + tx;
        T[o] = __float2half_rn(t[tx][ty + 8 * i]);
    }
}

// ---------------------------------------------------------------------------
// Shared GEMM core: tile (m0,n0) of C[?,N] = A[rows][K=1024] @ B[N,K]^T.
// BM=128, BN=256, BK=32, 256 threads, 4-stage cp.async.
// Output: fp16 single (Ch != null) or fp32 (C).
// ---------------------------------------------------------------------------
#define GBM 128
#define GBN 256
#define GBK 32
#define KD  1024
#define ITERS (KD / GBK)               // 32
#define RSB 80                         // 32 fp16 + 8 pad = 80 bytes/row
#define OFF_A   0
#define OFF_B   (GBM * RSB)            // 10240
#define STAGE_BYTES ((GBM + GBN) * RSB)  // 30720
#define NSTAGE  4
#define GEMM_SMEM (NSTAGE * STAGE_BYTES) // 122880

__device__ __forceinline__ void gemm_core(
    int m0, int n0, int N,
    const __half* __restrict__ A, const __half* __restrict__ B,
    const int* __restrict__ rowlist,
    float* __restrict__ C, __half* __restrict__ Ch,
    char* smem, int* srl)
{
    const uint32_t sb = smem_to_u32(smem);
    const int tid  = threadIdx.x;
    const int wid  = tid >> 5;
    const int lane = tid & 31;

    if (tid < GBM) srl[tid] = rowlist ? rowlist[m0 + tid] : (m0 + tid);
    __syncthreads();

    const int warp_m = (wid & 1) * 64;
    const int warp_n = (wid >> 1) * 64;

    float acc[4][8][4];
    #pragma unroll
    for (int i = 0; i < 4; i++)
        #pragma unroll
        for (int j = 0; j < 8; j++)
            #pragma unroll
            for (int q = 0; q < 4; q++) acc[i][j][q] = 0.0f;

    auto load_stage = [&](int it, int stage) {
        const uint32_t stg = sb + stage * STAGE_BYTES;
        const int k0 = it * GBK;
        #pragma unroll
        for (int i = 0; i < 6; i++) {
            int c = i * 256 + tid;
            const __half* g;
            uint32_t soff;
            if (c < 512) {             // A: 128 rows x 4 chunks
                int row = c >> 2, kc = c & 3;
                g = A + (size_t)srl[row] * KD + k0 + kc * 8;
                soff = OFF_A + row * RSB + kc * 16;
            } else {                   // B: 256 rows x 4 chunks
                int c2 = c - 512;
                int row = c2 >> 2, kc = c2 & 3;
                g = B + (size_t)(n0 + row) * KD + k0 + kc * 8;
                soff = OFF_B + row * RSB + kc * 16;
            }
            cp_async16(stg + soff, g);
        }
    };

    load_stage(0, 0); CP_COMMIT();
    load_stage(1, 1); CP_COMMIT();
    load_stage(2, 2); CP_COMMIT();

    const int a_row  = lane & 15;
    const int a_byte = (lane >> 4) << 4;
    const int b_row  = ((lane >> 4) << 3) + (lane & 7);
    const int b_byte = ((lane >> 3) & 1) << 4;

    #pragma unroll 1
    for (int it = 0; it < ITERS; ++it) {
        if (it + 1 >= ITERS)      { CP_WAIT(0); }
        else if (it + 2 >= ITERS) { CP_WAIT(1); }
        else                      { CP_WAIT(2); }
        __syncthreads();

        if (it + 3 < ITERS) {
            load_stage(it + 3, (it + 3) & (NSTAGE - 1));
            CP_COMMIT();
        }

        const uint32_t stg = sb + (it & (NSTAGE - 1)) * STAGE_BYTES;
        const uint32_t aARow = stg + (warp_m + a_row) * RSB + a_byte;
        const uint32_t aBRow = stg + (warp_n + b_row) * RSB + b_byte;

        #pragma unroll
        for (int kc = 0; kc < 2; kc++) {
            const uint32_t kb = kc * 32;
            uint32_t aa[4][4], bb[8][2];
            #pragma unroll
            for (int i = 0; i < 4; i++)
                ldsm_x4(aa[i][0], aa[i][1], aa[i][2], aa[i][3],
                        aARow + OFF_A + i * 16 * RSB + kb);
            #pragma unroll
            for (int jj = 0; jj < 4; jj++)
                ldsm_x4(bb[2*jj][0], bb[2*jj][1], bb[2*jj+1][0], bb[2*jj+1][1],
                        aBRow + OFF_B + jj * 16 * RSB + kb);
            #pragma unroll
            for (int i = 0; i < 4; i++)
                #pragma unroll
                for (int j = 0; j < 8; j++)
                    mma16816(acc[i][j], aa[i][0], aa[i][1], aa[i][2], aa[i][3],
                             bb[j][0], bb[j][1]);
        }
    }

    const int er = lane >> 2;
    const int ec = (lane & 3) * 2;
    if (Ch) {
        #pragma unroll
        for (int i = 0; i < 4; i++)
            #pragma unroll
            for (int j = 0; j < 8; j++) {
                int row = m0 + warp_m + i * 16 + er;
                int col = n0 + warp_n + j * 8 + ec;
                *(uint32_t*)(Ch + (size_t)row * N + col) =
                    pack_h2(acc[i][j][0], acc[i][j][1]);
                *(uint32_t*)(Ch + (size_t)(row + 8) * N + col) =
                    pack_h2(acc[i][j][2], acc[i][j][3]);
            }
    } else {
        #pragma unroll
        for (int i = 0; i < 4; i++)
            #pragma unroll
            for (int j = 0; j < 8; j++) {
                int row = m0 + warp_m + i * 16 + er;
                int col = n0 + warp_n + j * 8 + ec;
                float* p0 = C + (size_t)row * N + col;
                float* p1 = C + (size_t)(row + 8) * N + col;
                p0[0] = acc[i][j][0]; p0[1] = acc[i][j][1];
                p1[0] = acc[i][j][2]; p1[1] = acc[i][j][3];
            }
    }
}

// Merged Q + K/V projection: 1024 CTAs in one launch.
//   bx <  512: Q tile   (m = bx>>2, nt = bx&3;  N=1024, out g_q)
//   bx >= 512: KV tile  (m = t>>3,  nt = t&7;   N=2048, rowlist, out g_kv)
__global__ __launch_bounds__(256, 1) void gemm_qkv() {
    extern __shared__ char smem[];
    __shared__ int srl[GBM];
    int bx = blockIdx.x;
    if (bx < 512) {
        gemm_core((bx >> 2) * GBM, (bx & 3) * GBN, DM,
                  g_x, g_wq, nullptr, nullptr, g_q, smem, srl);
    } else {
        int t = bx - 512;
        gemm_core((t >> 3) * GBM, (t & 7) * GBN, 2 * DM,
                  g_x, g_wq + (size_t)DM * DM, g_rowkv,
                  nullptr, g_kv, smem, srl);
    }
}

// Output projection -> fp32
__global__ __launch_bounds__(256, 1) void gemm_out(float* __restrict__ C) {
    extern __shared__ char smem[];
    __shared__ int srl[GBM];
    int bx = blockIdx.x;                  // 512 tiles: m = bx>>2, nt = bx&3
    gemm_core((bx >> 2) * GBM, (bx & 3) * GBN, DM,
              g_a, g_wo, nullptr, C, nullptr, smem, srl);
}

// ---------------------------------------------------------------------------
// Tensor-core segment attention (fp16 HMMA, softmax in fragments).
// Q single fp16, K/V single fp16, P exact split for P@V.
// One block per (b, h, seg): 128 threads = 4 warps, 32 q-rows per warp.
// smem: swizzled fp16 tiles Q[128x64], K[64x64], V[64x64] = 32KB.
// ---------------------------------------------------------------------------
#define ASM_Q  0
#define ASM_K  16384
#define ASM_V  24576
#define ATTN_SMEM 32768
// swizzled address within a tile: row stride 128B, 16B chunks XOR'd by row&7
#define SWIZ(base, row, ch) ((base) + (row) * 128 + ((((ch) ^ ((row) & 7))) << 4))

__global__ __launch_bounds__(128) void attn_kernel() {
    extern __shared__ char asmem[];
    const uint32_t sb = smem_to_u32(asmem);

    const int bid = blockIdx.x;
    const int n = bid % NSEG;
    const int h = (bid / NSEG) % NH;
    const int b = bid / (NSEG * NH);
    const int tid = threadIdx.x;
    const int lane = tid & 31;
    const int wid = tid >> 5;
    const int warp_m = wid * 32;

    // ---- load Q: 1024 16B chunks ----
    #pragma unroll
    for (int i = 0; i < 8; i++) {
        int c = i * 128 + tid;
        int row = c >> 3, ch = c & 7;
        int sq = hmap(n * SEG + row);
        const __half* g = g_q + ((size_t)(b * S_LEN + sq)) * DM + h * DH + ch * 8;
        cp_async16(SWIZ(sb + ASM_Q, row, ch), g);
    }
    // ---- load K and V: 1024 16B chunks ----
    #pragma unroll
    for (int i = 0; i < 8; i++) {
        int c = i * 128 + tid;
        int kv  = c >> 9;               // 0=K 1=V
        int rc  = c & 511;
        int row = rc >> 3, ch = rc & 7;
        size_t go = ((size_t)b * 4096 + n * 64 + row) * (2 * DM)
                  + (size_t)kv * DM + h * DH + ch * 8;
        cp_async16(SWIZ(sb + (kv ? ASM_V : ASM_K), row, ch), g_kv + go);
    }
    CP_COMMIT();
    CP_WAIT(0);
    __syncthreads();

    // ---- scores: S = Q @ K^T ----
    float acc_s[2][8][4];
    #pragma unroll
    for (int i = 0; i < 2; i++)
        #pragma unroll
        for (int j = 0; j < 8; j++)
            #pragma unroll
            for (int q = 0; q < 4; q++) acc_s[i][j][q] = 0.0f;

    const int a_r  = lane & 15;
    const int a_c  = lane >> 4;
    const int b_r  = ((lane >> 4) << 3) + (lane & 7);
    const int b_c  = (lane >> 3) & 1;

    #pragma unroll
    for (int t = 0; t < 4; t++) {
        uint32_t qq[2][4], kk[8][2];
        #pragma unroll
        for (int i = 0; i < 2; i++) {
            int row = warp_m + i * 16 + a_r;
            int ch = 2 * t + a_c;
            ldsm_x4(qq[i][0], qq[i][1], qq[i][2], qq[i][3],
                    SWIZ(sb + ASM_Q, row, ch));
        }
        #pragma unroll
        for (int jj = 0; jj < 4; jj++) {
            int row = jj * 16 + b_r;
            int ch = 2 * t + b_c;
            ldsm_x4(kk[2*jj][0], kk[2*jj][1], kk[2*jj+1][0], kk[2*jj+1][1],
                    SWIZ(sb + ASM_K, row, ch));
        }
        #pragma unroll
        for (int i = 0; i < 2; i++)
            #pragma unroll
            for (int j = 0; j < 8; j++)
                mma16816(acc_s[i][j], qq[i][0], qq[i][1], qq[i][2], qq[i][3],
                         kk[j][0], kk[j][1]);
    }

    // ---- softmax over 64 cols, per fragment row (quad shfl reduce) ----
    #pragma unroll
    for (int i = 0; i < 2; i++) {
        #pragma unroll
        for (int half = 0; half < 2; half++) {
            float mx = -1e30f;
            #pragma unroll
            for (int j = 0; j < 8; j++) {
                mx = fmaxf(mx, acc_s[i][j][half*2]);
                mx = fmaxf(mx, acc_s[i][j][half*2+1]);
            }
            mx = fmaxf(mx, __shfl_xor_sync(0xffffffffu, mx, 1));
            mx = fmaxf(mx, __shfl_xor_sync(0xffffffffu, mx, 2));
            float sum = 0.0f;
            #pragma unroll
            for (int j = 0; j < 8; j++) {
                float p0 = expf((acc_s[i][j][half*2]   - mx) * 0.125f);
                float p1 = expf((acc_s[i][j][half*2+1] - mx) * 0.125f);
                acc_s[i][j][half*2]   = p0;
                acc_s[i][j][half*2+1] = p1;
                sum += p0 + p1;
            }
            sum += __shfl_xor_sync(0xffffffffu, sum, 1);
            sum += __shfl_xor_sync(0xffffffffu, sum, 2);
            float inv = 1.0f / sum;
            #pragma unroll
            for (int j = 0; j < 8; j++) {
                acc_s[i][j][half*2]   *= inv;
                acc_s[i][j][half*2+1] *= inv;
            }
        }
    }

    // ---- O = P @ V  (P split fp16 in frags, V^T frags via ldmatrix.trans) ----
    float acc_o[2][8][4];
    #pragma unroll
    for (int i = 0; i < 2; i++)
        #pragma unroll
        for (int j = 0; j < 8; j++)
            #pragma unroll
            for (int q = 0; q < 4; q++) acc_o[i][j][q] = 0.0f;

    #pragma unroll
    for (int t = 0; t < 4; t++) {
        uint32_t ph[2][4], pl[2][4];
        #pragma unroll
        for (int i = 0; i < 2; i++) {
            pack_split_h(acc_s[i][2*t][0],   acc_s[i][2*t][1],   ph[i][0], pl[i][0]);
            pack_split_h(acc_s[i][2*t][2],   acc_s[i][2*t][3],   ph[i][1], pl[i][1]);
            pack_split_h(acc_s[i][2*t+1][0], acc_s[i][2*t+1][1], ph[i][2], pl[i][2]);
            pack_split_h(acc_s[i][2*t+1][2], acc_s[i][2*t+1][3], ph[i][3], pl[i][3]);
        }
        uint32_t vv[8][2];
        #pragma unroll
        for (int jj = 0; jj < 4; jj++) {
            int row = t * 16 + (lane & 15);
            int ch = jj * 2 + (lane >> 4);
            ldsm_x4_t(vv[2*jj][0], vv[2*jj][1], vv[2*jj+1][0], vv[2*jj+1][1],
                      SWIZ(sb + ASM_V, row, ch));
        }
        #pragma unroll
        for (int i = 0; i < 2; i++)
            #pragma unroll
            for (int nd = 0; nd < 8; nd++) {
                mma16816(acc_o[i][nd], ph[i][0], ph[i][1], ph[i][2], ph[i][3],
                         vv[nd][0], vv[nd][1]);
                mma16816(acc_o[i][nd], pl[i][0], pl[i][1], pl[i][2], pl[i][3],
                         vv[nd][0], vv[nd][1]);
            }
    }

    // ---- epilogue: scatter rows back by map, write single fp16 ----
    const int er = lane >> 2;
    const int ec = (lane & 3) * 2;
    #pragma unroll
    for (int i = 0; i < 2; i++) {
        #pragma unroll
        for (int half = 0; half < 2; half++) {
            int rowl = warp_m + i * 16 + er + half * 8;
            int sq = hmap(n * SEG + rowl);
            size_t gr = ((size_t)(b * S_LEN + sq)) * DM + h * DH;
            #pragma unroll
            for (int nd = 0; nd < 8; nd++) {
                *(uint32_t*)(g_a + gr + nd * 8 + ec) =
                    pack_h2(acc_o[i][nd][half*2], acc_o[i][nd][half*2+1]);
            }
        }
    }
}

// ---------------------------------------------------------------------------
// Launch
// ---------------------------------------------------------------------------
extern "C" void kernel_launch(void* const* d_in, const int* in_sizes, int n_in,
                              void* d_out, int out_size)
{
    const float* x    = (const float*)d_in[0];   // [2,8192,1024]
    const float* wqkv = (const float*)d_in[1];   // [1024,3072]
    const float* wout = (const float*)d_in[2];   // [1024,1024]
    float*       out  = (float*)d_out;           // [2,8192,1024]

    __half *xp, *wq, *wo;
    cudaGetSymbolAddress((void**)&xp, g_x);
    cudaGetSymbolAddress((void**)&wq, g_wq);
    cudaGetSymbolAddress((void**)&wo, g_wo);

    static bool attr_set = false;
    if (!attr_set) {
        cudaFuncSetAttribute(gemm_qkv,
            cudaFuncAttributeMaxDynamicSharedMemorySize, GEMM_SMEM);
        cudaFuncSetAttribute(gemm_out,
            cudaFuncAttributeMaxDynamicSharedMemorySize, GEMM_SMEM);
        cudaFuncSetAttribute(attn_kernel,
            cudaFuncAttributeMaxDynamicSharedMemorySize, ATTN_SMEM);
        attr_set = true;
    }

    // 1. prep
    rowkv_kernel<<<(KVROWS + 255) / 256, 256>>>();
    cvt_kernel<<<(MROWS * DM / 4 + 255) / 256, 256>>>(x, xp, MROWS * DM / 4);
    {
        dim3 blk(32, 8);
        transpose_h_kernel<<<dim3(3 * DM / 32, DM / 32), blk>>>(wqkv, wq, DM, 3 * DM);
        transpose_h_kernel<<<dim3(DM / 32, DM / 32), blk>>>(wout, wo, DM, DM);
    }

    // 2. merged Q + K/V projections (1024 CTAs, one launch)
    gemm_qkv<<<1024, 256, GEMM_SMEM>>>();

    // 3. tensor-core segment attention -> fp16 single
    attn_kernel<<<B_SZ * NH * NSEG, 128, ATTN_SMEM>>>();

    // 4. output projection -> fp32 final
    gemm_out<<<512, 256, GEMM_SMEM>>>(out);
}

// round 9
// speedup vs baseline: 6.6845x; 1.0120x over previous
#include <cuda_runtime.h>
#include <cuda_fp16.h>
#include <cstdint>
#include <math.h>

// Problem constants (fixed by the dataset)
#define S_LEN  8192
#define B_SZ   2
#define DM     1024
#define NH     16
#define DH     64
#define SEG    128
#define NSEG   (S_LEN / SEG)     // 64
#define GRID_G 91                // ceil(sqrt(8192))

#define MROWS  (B_SZ * S_LEN)      // 16384
#define KVROWS (B_SZ * S_LEN / 2)  // 8192 compacted K/V rows

// ---------------------------------------------------------------------------
// Scratch (allocation-free rule: __device__ globals)
// ---------------------------------------------------------------------------
__device__ __half  g_x   [MROWS * DM];          // x fp16
__device__ __half  g_q   [MROWS * DM];          // Q fp16 single
__device__ __half  g_kv  [KVROWS * 2 * DM];     // compact [K|V] fp16
__device__ __half  g_a   [MROWS * DM];          // attn-out fp16
__device__ __half  g_wq  [3 * DM * DM];         // W_qkv^T fp16 [3072,1024]
__device__ __half  g_wo  [DM * DM];             // W_out^T fp16 [1024,1024]
__device__ int     g_rowkv[KVROWS];             // gathered A rows for K/V GEMM

// ---------------------------------------------------------------------------
// PTX helpers (compute_103-safe subset: ldmatrix / mma.sync / cp.async)
// ---------------------------------------------------------------------------
__device__ __forceinline__ uint32_t smem_to_u32(const void* p) {
    uint32_t a;
    asm("{ .reg .u64 t; cvta.to.shared.u64 t, %1; cvt.u32.u64 %0, t; }"
        : "=r"(a) : "l"(p));
    return a;
}
__device__ __forceinline__ void cp_async16(uint32_t saddr, const void* gptr) {
    asm volatile("cp.async.cg.shared.global [%0], [%1], 16;"
                 :: "r"(saddr), "l"(gptr));
}
#define CP_COMMIT() asm volatile("cp.async.commit_group;")
#define CP_WAIT(n)  asm volatile("cp.async.wait_group %0;" :: "n"(n))

__device__ __forceinline__ void ldsm_x4(uint32_t& r0, uint32_t& r1,
                                        uint32_t& r2, uint32_t& r3,
                                        uint32_t addr) {
    asm volatile("ldmatrix.sync.aligned.m8n8.x4.shared.b16 {%0,%1,%2,%3}, [%4];"
                 : "=r"(r0), "=r"(r1), "=r"(r2), "=r"(r3) : "r"(addr));
}
__device__ __forceinline__ void ldsm_x4_t(uint32_t& r0, uint32_t& r1,
                                          uint32_t& r2, uint32_t& r3,
                                          uint32_t addr) {
    asm volatile("ldmatrix.sync.aligned.m8n8.x4.trans.shared.b16 {%0,%1,%2,%3}, [%4];"
                 : "=r"(r0), "=r"(r1), "=r"(r2), "=r"(r3) : "r"(addr));
}
__device__ __forceinline__ void mma16816(float* c,
                                         uint32_t a0, uint32_t a1,
                                         uint32_t a2, uint32_t a3,
                                         uint32_t b0, uint32_t b1) {
    asm volatile(
        "mma.sync.aligned.m16n8k16.row.col.f32.f16.f16.f32 "
        "{%0,%1,%2,%3}, {%4,%5,%6,%7}, {%8,%9}, {%0,%1,%2,%3};"
        : "+f"(c[0]), "+f"(c[1]), "+f"(c[2]), "+f"(c[3])
        : "r"(a0), "r"(a1), "r"(a2), "r"(a3), "r"(b0), "r"(b1));
}

__device__ __forceinline__ uint32_t pack_h2(float a, float b) {
    __half2 t = __halves2half2(__float2half_rn(a), __float2half_rn(b));
    return *(uint32_t*)&t;
}

// ---------------------------------------------------------------------------
// Closed-form boustrophedon map
// ---------------------------------------------------------------------------
__device__ __forceinline__ int hmap(int lp) {
    int r = lp / GRID_G;
    int c = lp % GRID_G;
    int vr = min(GRID_G, S_LEN - r * GRID_G);
    return ((r & 1) == 0) ? (r * GRID_G + c) : (r * GRID_G + vr - 1 - c);
}

// ---------------------------------------------------------------------------
// Merged prep: cvt (16384 blocks) | W_qkv^T (3072) | W_out^T (1024) | rowkv (32)
// All blocks 256 threads.
// ---------------------------------------------------------------------------
#define PREP_CVT_BLKS   16384
#define PREP_TQ_BLKS    3072
#define PREP_TO_BLKS    1024
#define PREP_RK_BLKS    32
#define PREP_BLKS (PREP_CVT_BLKS + PREP_TQ_BLKS + PREP_TO_BLKS + PREP_RK_BLKS)

__global__ __launch_bounds__(256) void prep_kernel(
    const float* __restrict__ x,
    const float* __restrict__ wqkv,
    const float* __restrict__ wout)
{
    __shared__ float t[32][33];
    const int bx = blockIdx.x;
    const int tid = threadIdx.x;

    if (bx < PREP_CVT_BLKS) {
        // fp32 -> fp16 convert of x
        int i = bx * 256 + tid;      // < MROWS*DM/4 exactly
        float4 v = ((const float4*)x)[i];
        ((uint32_t*)g_x)[2 * i]     = pack_h2(v.x, v.y);
        ((uint32_t*)g_x)[2 * i + 1] = pack_h2(v.z, v.w);
        return;
    }
    if (bx < PREP_CVT_BLKS + PREP_TQ_BLKS + PREP_TO_BLKS) {
        // tiled transpose + cvt of W_qkv (N=3072) or W_out (N=1024)
        const float* W; __half* T; int N, tb;
        if (bx < PREP_CVT_BLKS + PREP_TQ_BLKS) {
            W = wqkv; T = g_wq; N = 3 * DM; tb = bx - PREP_CVT_BLKS;
        } else {
            W = wout; T = g_wo; N = DM; tb = bx - PREP_CVT_BLKS - PREP_TQ_BLKS;
        }
        int nblk = N / 32;
        int n0 = (tb % nblk) * 32, k0 = (tb / nblk) * 32;
        int tx = tid & 31, ty = tid >> 5;   // (32, 8)
        #pragma unroll
        for (int i = 0; i < 4; i++)
            t[ty + 8 * i][tx] = W[(size_t)(k0 + ty + 8 * i) * N + n0 + tx];
        __syncthreads();
        #pragma unroll
        for (int i = 0; i < 4; i++) {
            size_t o = (size_t)(n0 + ty + 8 * i) * DM + k0 + tx;
            T[o] = __float2half_rn(t[tx][ty + 8 * i]);
        }
        return;
    }
    // rowkv
    int i = (bx - (PREP_BLKS - PREP_RK_BLKS)) * 256 + tid;  // < KVROWS exactly
    int b = i >> 12;
    int r = i & 4095;
    int n = r >> 6, j = r & 63;
    g_rowkv[i] = b * S_LEN + hmap(n * SEG + 2 * j);
}

// ---------------------------------------------------------------------------
// GEMM core (BN=256): tile (m0,n0) of C[?,N] = A[rows][1024] @ B[N,1024]^T
// BM=128, BK=32, 256 threads, 4-stage cp.async. fp16-single output.
// ---------------------------------------------------------------------------
#define GBM 128
#define GBK 32
#define KD  1024
#define ITERS (KD / GBK)               // 32
#define RSB 80                         // 32 fp16 + 8 pad = 80 bytes/row
#define NSTAGE  4

#define OFF_B256   (GBM * RSB)              // 10240
#define STAGE256   ((GBM + 256) * RSB)      // 30720
#define SMEM256    (NSTAGE * STAGE256)      // 122880

__device__ __forceinline__ void gemm_core256(
    int m0, int n0, int N,
    const __half* __restrict__ A, const __half* __restrict__ B,
    const int* __restrict__ rowlist,
    __half* __restrict__ Ch,
    char* smem, int* srl)
{
    const uint32_t sb = smem_to_u32(smem);
    const int tid  = threadIdx.x;
    const int wid  = tid >> 5;
    const int lane = tid & 31;

    if (tid < GBM) srl[tid] = rowlist ? rowlist[m0 + tid] : (m0 + tid);
    __syncthreads();

    const int warp_m = (wid & 1) * 64;
    const int warp_n = (wid >> 1) * 64;

    float acc[4][8][4];
    #pragma unroll
    for (int i = 0; i < 4; i++)
        #pragma unroll
        for (int j = 0; j < 8; j++)
            #pragma unroll
            for (int q = 0; q < 4; q++) acc[i][j][q] = 0.0f;

    auto load_stage = [&](int it, int stage) {
        const uint32_t stg = sb + stage * STAGE256;
        const int k0 = it * GBK;
        #pragma unroll
        for (int i = 0; i < 6; i++) {
            int c = i * 256 + tid;
            const __half* g;
            uint32_t soff;
            if (c < 512) {
                int row = c >> 2, kc = c & 3;
                g = A + (size_t)srl[row] * KD + k0 + kc * 8;
                soff = row * RSB + kc * 16;
            } else {
                int c2 = c - 512;
                int row = c2 >> 2, kc = c2 & 3;
                g = B + (size_t)(n0 + row) * KD + k0 + kc * 8;
                soff = OFF_B256 + row * RSB + kc * 16;
            }
            cp_async16(stg + soff, g);
        }
    };

    load_stage(0, 0); CP_COMMIT();
    load_stage(1, 1); CP_COMMIT();
    load_stage(2, 2); CP_COMMIT();

    const int a_row  = lane & 15;
    const int a_byte = (lane >> 4) << 4;
    const int b_row  = ((lane >> 4) << 3) + (lane & 7);
    const int b_byte = ((lane >> 3) & 1) << 4;

    #pragma unroll 1
    for (int it = 0; it < ITERS; ++it) {
        if (it + 1 >= ITERS)      { CP_WAIT(0); }
        else if (it + 2 >= ITERS) { CP_WAIT(1); }
        else                      { CP_WAIT(2); }
        __syncthreads();

        if (it + 3 < ITERS) {
            load_stage(it + 3, (it + 3) & (NSTAGE - 1));
            CP_COMMIT();
        }

        const uint32_t stg = sb + (it & (NSTAGE - 1)) * STAGE256;
        const uint32_t aARow = stg + (warp_m + a_row) * RSB + a_byte;
        const uint32_t aBRow = stg + OFF_B256 + (warp_n + b_row) * RSB + b_byte;

        #pragma unroll
        for (int kc = 0; kc < 2; kc++) {
            const uint32_t kb = kc * 32;
            uint32_t aa[4][4], bb[8][2];
            #pragma unroll
            for (int i = 0; i < 4; i++)
                ldsm_x4(aa[i][0], aa[i][1], aa[i][2], aa[i][3],
                        aARow + i * 16 * RSB + kb);
            #pragma unroll
            for (int jj = 0; jj < 4; jj++)
                ldsm_x4(bb[2*jj][0], bb[2*jj][1], bb[2*jj+1][0], bb[2*jj+1][1],
                        aBRow + jj * 16 * RSB + kb);
            #pragma unroll
            for (int i = 0; i < 4; i++)
                #pragma unroll
                for (int j = 0; j < 8; j++)
                    mma16816(acc[i][j], aa[i][0], aa[i][1], aa[i][2], aa[i][3],
                             bb[j][0], bb[j][1]);
        }
    }

    const int er = lane >> 2;
    const int ec = (lane & 3) * 2;
    #pragma unroll
    for (int i = 0; i < 4; i++)
        #pragma unroll
        for (int j = 0; j < 8; j++) {
            int row = m0 + warp_m + i * 16 + er;
            int col = n0 + warp_n + j * 8 + ec;
            *(uint32_t*)(Ch + (size_t)row * N + col) =
                pack_h2(acc[i][j][0], acc[i][j][1]);
            *(uint32_t*)(Ch + (size_t)(row + 8) * N + col) =
                pack_h2(acc[i][j][2], acc[i][j][3]);
        }
}

// Merged Q + K/V projection: 1024 CTAs.
__global__ __launch_bounds__(256, 1) void gemm_qkv() {
    extern __shared__ char smem[];
    __shared__ int srl[GBM];
    int bx = blockIdx.x;
    if (bx < 512) {
        gemm_core256((bx >> 2) * GBM, (bx & 3) * 256, DM,
                     g_x, g_wq, nullptr, g_q, smem, srl);
    } else {
        int t = bx - 512;
        gemm_core256((t >> 3) * GBM, (t & 7) * 256, 2 * DM,
                     g_x, g_wq + (size_t)DM * DM, g_rowkv, g_kv, smem, srl);
    }
}

// ---------------------------------------------------------------------------
// Output projection (BN=128 -> 1024 CTAs, ~1% wave tail), fp32 out.
// Warp tile 64x32: warp_m = (wid&1)*64, warp_n = (wid>>1)*32.
// ---------------------------------------------------------------------------
#define OFF_B128   (GBM * RSB)              // 10240
#define STAGE128   ((GBM + 128) * RSB)      // 20480
#define SMEM128    (NSTAGE * STAGE128)      // 81920

__global__ __launch_bounds__(256, 1) void gemm_out(float* __restrict__ C) {
    extern __shared__ char smem[];
    const uint32_t sb = smem_to_u32(smem);
    const int tid  = threadIdx.x;
    const int wid  = tid >> 5;
    const int lane = tid & 31;

    const int m0 = (blockIdx.x >> 3) * GBM;
    const int n0 = (blockIdx.x & 7) * 128;

    const int warp_m = (wid & 1) * 64;
    const int warp_n = (wid >> 1) * 32;

    float acc[4][4][4];
    #pragma unroll
    for (int i = 0; i < 4; i++)
        #pragma unroll
        for (int j = 0; j < 4; j++)
            #pragma unroll
            for (int q = 0; q < 4; q++) acc[i][j][q] = 0.0f;

    auto load_stage = [&](int it, int stage) {
        const uint32_t stg = sb + stage * STAGE128;
        const int k0 = it * GBK;
        #pragma unroll
        for (int i = 0; i < 4; i++) {
            int c = i * 256 + tid;
            const __half* g;
            uint32_t soff;
            if (c < 512) {
                int row = c >> 2, kc = c & 3;
                g = g_a + (size_t)(m0 + row) * KD + k0 + kc * 8;
                soff = row * RSB + kc * 16;
            } else {
                int c2 = c - 512;
                int row = c2 >> 2, kc = c2 & 3;
                g = g_wo + (size_t)(n0 + row) * KD + k0 + kc * 8;
                soff = OFF_B128 + row * RSB + kc * 16;
            }
            cp_async16(stg + soff, g);
        }
    };

    load_stage(0, 0); CP_COMMIT();
    load_stage(1, 1); CP_COMMIT();
    load_stage(2, 2); CP_COMMIT();

    const int a_row  = lane & 15;
    const int a_byte = (lane >> 4) << 4;
    const int b_row  = ((lane >> 4) << 3) + (lane & 7);
    const int b_byte = ((lane >> 3) & 1) << 4;

    #pragma unroll 1
    for (int it = 0; it < ITERS; ++it) {
        if (it + 1 >= ITERS)      { CP_WAIT(0); }
        else if (it + 2 >= ITERS) { CP_WAIT(1); }
        else                      { CP_WAIT(2); }
        __syncthreads();

        if (it + 3 < ITERS) {
            load_stage(it + 3, (it + 3) & (NSTAGE - 1));
            CP_COMMIT();
        }

        const uint32_t stg = sb + (it & (NSTAGE - 1)) * STAGE128;
        const uint32_t aARow = stg + (warp_m + a_row) * RSB + a_byte;
        const uint32_t aBRow = stg + OFF_B128 + (warp_n + b_row) * RSB + b_byte;

        #pragma unroll
        for (int kc = 0; kc < 2; kc++) {
            const uint32_t kb = kc * 32;
            uint32_t aa[4][4], bb[4][2];
            #pragma unroll
            for (int i = 0; i < 4; i++)
                ldsm_x4(aa[i][0], aa[i][1], aa[i][2], aa[i][3],
                        aARow + i * 16 * RSB + kb);
            #pragma unroll
            for (int jj = 0; jj < 2; jj++)
                ldsm_x4(bb[2*jj][0], bb[2*jj][1], bb[2*jj+1][0], bb[2*jj+1][1],
                        aBRow + jj * 16 * RSB + kb);
            #pragma unroll
            for (int i = 0; i < 4; i++)
                #pragma unroll
                for (int j = 0; j < 4; j++)
                    mma16816(acc[i][j], aa[i][0], aa[i][1], aa[i][2], aa[i][3],
                             bb[j][0], bb[j][1]);
        }
    }

    const int er = lane >> 2;
    const int ec = (lane & 3) * 2;
    #pragma unroll
    for (int i = 0; i < 4; i++)
        #pragma unroll
        for (int j = 0; j < 4; j++) {
            int row = m0 + warp_m + i * 16 + er;
            int col = n0 + warp_n + j * 8 + ec;
            float* p0 = C + (size_t)row * DM + col;
            float* p1 = C + (size_t)(row + 8) * DM + col;
            p0[0] = acc[i][j][0]; p0[1] = acc[i][j][1];
            p1[0] = acc[i][j][2]; p1[1] = acc[i][j][3];
        }
}

// ---------------------------------------------------------------------------
// Tensor-core segment attention (fp16 HMMA, softmax in fragments).
// Q, K, V, P all single fp16.  One block per (b, h, seg): 128 threads.
// smem: swizzled fp16 tiles Q[128x64], K[64x64], V[64x64] = 32KB.
// ---------------------------------------------------------------------------
#define ASM_Q  0
#define ASM_K  16384
#define ASM_V  24576
#define ATTN_SMEM 32768
#define SWIZ(base, row, ch) ((base) + (row) * 128 + ((((ch) ^ ((row) & 7))) << 4))

__global__ __launch_bounds__(128) void attn_kernel() {
    extern __shared__ char asmem[];
    const uint32_t sb = smem_to_u32(asmem);

    const int bid = blockIdx.x;
    const int n = bid % NSEG;
    const int h = (bid / NSEG) % NH;
    const int b = bid / (NSEG * NH);
    const int tid = threadIdx.x;
    const int lane = tid & 31;
    const int wid = tid >> 5;
    const int warp_m = wid * 32;

    // ---- load Q: 1024 16B chunks ----
    #pragma unroll
    for (int i = 0; i < 8; i++) {
        int c = i * 128 + tid;
        int row = c >> 3, ch = c & 7;
        int sq = hmap(n * SEG + row);
        const __half* g = g_q + ((size_t)(b * S_LEN + sq)) * DM + h * DH + ch * 8;
        cp_async16(SWIZ(sb + ASM_Q, row, ch), g);
    }
    // ---- load K and V: 1024 16B chunks ----
    #pragma unroll
    for (int i = 0; i < 8; i++) {
        int c = i * 128 + tid;
        int kv  = c >> 9;
        int rc  = c & 511;
        int row = rc >> 3, ch = rc & 7;
        size_t go = ((size_t)b * 4096 + n * 64 + row) * (2 * DM)
                  + (size_t)kv * DM + h * DH + ch * 8;
        cp_async16(SWIZ(sb + (kv ? ASM_V : ASM_K), row, ch), g_kv + go);
    }
    CP_COMMIT();
    CP_WAIT(0);
    __syncthreads();

    // ---- scores: S = Q @ K^T ----
    float acc_s[2][8][4];
    #pragma unroll
    for (int i = 0; i < 2; i++)
        #pragma unroll
        for (int j = 0; j < 8; j++)
            #pragma unroll
            for (int q = 0; q < 4; q++) acc_s[i][j][q] = 0.0f;

    const int a_r  = lane & 15;
    const int a_c  = lane >> 4;
    const int b_r  = ((lane >> 4) << 3) + (lane & 7);
    const int b_c  = (lane >> 3) & 1;

    #pragma unroll
    for (int t = 0; t < 4; t++) {
        uint32_t qq[2][4], kk[8][2];
        #pragma unroll
        for (int i = 0; i < 2; i++) {
            int row = warp_m + i * 16 + a_r;
            int ch = 2 * t + a_c;
            ldsm_x4(qq[i][0], qq[i][1], qq[i][2], qq[i][3],
                    SWIZ(sb + ASM_Q, row, ch));
        }
        #pragma unroll
        for (int jj = 0; jj < 4; jj++) {
            int row = jj * 16 + b_r;
            int ch = 2 * t + b_c;
            ldsm_x4(kk[2*jj][0], kk[2*jj][1], kk[2*jj+1][0], kk[2*jj+1][1],
                    SWIZ(sb + ASM_K, row, ch));
        }
        #pragma unroll
        for (int i = 0; i < 2; i++)
            #pragma unroll
            for (int j = 0; j < 8; j++)
                mma16816(acc_s[i][j], qq[i][0], qq[i][1], qq[i][2], qq[i][3],
                         kk[j][0], kk[j][1]);
    }

    // ---- softmax over 64 cols, per fragment row (quad shfl reduce) ----
    #pragma unroll
    for (int i = 0; i < 2; i++) {
        #pragma unroll
        for (int half = 0; half < 2; half++) {
            float mx = -1e30f;
            #pragma unroll
            for (int j = 0; j < 8; j++) {
                mx = fmaxf(mx, acc_s[i][j][half*2]);
                mx = fmaxf(mx, acc_s[i][j][half*2+1]);
            }
            mx = fmaxf(mx, __shfl_xor_sync(0xffffffffu, mx, 1));
            mx = fmaxf(mx, __shfl_xor_sync(0xffffffffu, mx, 2));
            float sum = 0.0f;
            #pragma unroll
            for (int j = 0; j < 8; j++) {
                float p0 = expf((acc_s[i][j][half*2]   - mx) * 0.125f);
                float p1 = expf((acc_s[i][j][half*2+1] - mx) * 0.125f);
                acc_s[i][j][half*2]   = p0;
                acc_s[i][j][half*2+1] = p1;
                sum += p0 + p1;
            }
            sum += __shfl_xor_sync(0xffffffffu, sum, 1);
            sum += __shfl_xor_sync(0xffffffffu, sum, 2);
            float inv = 1.0f / sum;
            #pragma unroll
            for (int j = 0; j < 8; j++) {
                acc_s[i][j][half*2]   *= inv;
                acc_s[i][j][half*2+1] *= inv;
            }
        }
    }

    // ---- O = P @ V  (P single fp16 in frags, V^T via ldmatrix.trans) ----
    float acc_o[2][8][4];
    #pragma unroll
    for (int i = 0; i < 2; i++)
        #pragma unroll
        for (int j = 0; j < 8; j++)
            #pragma unroll
            for (int q = 0; q < 4; q++) acc_o[i][j][q] = 0.0f;

    #pragma unroll
    for (int t = 0; t < 4; t++) {
        uint32_t pp[2][4];
        #pragma unroll
        for (int i = 0; i < 2; i++) {
            pp[i][0] = pack_h2(acc_s[i][2*t][0],   acc_s[i][2*t][1]);
            pp[i][1] = pack_h2(acc_s[i][2*t][2],   acc_s[i][2*t][3]);
            pp[i][2] = pack_h2(acc_s[i][2*t+1][0], acc_s[i][2*t+1][1]);
            pp[i][3] = pack_h2(acc_s[i][2*t+1][2], acc_s[i][2*t+1][3]);
        }
        uint32_t vv[8][2];
        #pragma unroll
        for (int jj = 0; jj < 4; jj++) {
            int row = t * 16 + (lane & 15);
            int ch = jj * 2 + (lane >> 4);
            ldsm_x4_t(vv[2*jj][0], vv[2*jj][1], vv[2*jj+1][0], vv[2*jj+1][1],
                      SWIZ(sb + ASM_V, row, ch));
        }
        #pragma unroll
        for (int i = 0; i < 2; i++)
            #pragma unroll
            for (int nd = 0; nd < 8; nd++)
                mma16816(acc_o[i][nd], pp[i][0], pp[i][1], pp[i][2], pp[i][3],
                         vv[nd][0], vv[nd][1]);
    }

    // ---- epilogue: scatter rows back by map, write single fp16 ----
    const int er = lane >> 2;
    const int ec = (lane & 3) * 2;
    #pragma unroll
    for (int i = 0; i < 2; i++) {
        #pragma unroll
        for (int half = 0; half < 2; half++) {
            int rowl = warp_m + i * 16 + er + half * 8;
            int sq = hmap(n * SEG + rowl);
            size_t gr = ((size_t)(b * S_LEN + sq)) * DM + h * DH;
            #pragma unroll
            for (int nd = 0; nd < 8; nd++) {
                *(uint32_t*)(g_a + gr + nd * 8 + ec) =
                    pack_h2(acc_o[i][nd][half*2], acc_o[i][nd][half*2+1]);
            }
        }
    }
}

// ---------------------------------------------------------------------------
// Launch
// ---------------------------------------------------------------------------
extern "C" void kernel_launch(void* const* d_in, const int* in_sizes, int n_in,
                              void* d_out, int out_size)
{
    const float* x    = (const float*)d_in[0];   // [2,8192,1024]
    const float* wqkv = (const float*)d_in[1];   // [1024,3072]
    const float* wout = (const float*)d_in[2];   // [1024,1024]
    float*       out  = (float*)d_out;           // [2,8192,1024]

    static bool attr_set = false;
    if (!attr_set) {
        cudaFuncSetAttribute(gemm_qkv,
            cudaFuncAttributeMaxDynamicSharedMemorySize, SMEM256);
        cudaFuncSetAttribute(gemm_out,
            cudaFuncAttributeMaxDynamicSharedMemorySize, SMEM128);
        cudaFuncSetAttribute(attn_kernel,
            cudaFuncAttributeMaxDynamicSharedMemorySize, ATTN_SMEM);
        attr_set = true;
    }

    // 1. merged prep (one launch)
    prep_kernel<<<PREP_BLKS, 256>>>(x, wqkv, wout);

    // 2. merged Q + K/V projections (1024 CTAs)
    gemm_qkv<<<1024, 256, SMEM256>>>();

    // 3. tensor-core segment attention -> fp16 single
    attn_kernel<<<B_SZ * NH * NSEG, 128, ATTN_SMEM>>>();

    // 4. output projection -> fp32 final (1024 CTAs, BN=128)
    gemm_out<<<1024, 256, SMEM128>>>(out);
}